// round 6
// baseline (speedup 1.0000x reference)
#include <cuda_runtime.h>
#include <math.h>
#include <stdint.h>

#define GX 272
#define GY 112
#define GZ 272
#define NCELL 8286208u            /* GX*GY*GZ */
#define NC2   73984               /* GX*GZ    */
#define RESF  0.03f
#define NROWS 1024
#define NPROP 256

/* ------------- static device scratch (no allocations) ------------- */
__device__ float    g_grid[4u*NCELL];   /* [obj | sx | sy | sz] */
__device__ float    g_cs[72];
__device__ float    g_dist[NC2];
__device__ float    g_logd[NC2];
__device__ int      g_yidx[NC2];
__device__ unsigned g_bth[NC2];
__device__ float    g_D;
__device__ int      g_sample[NROWS];
__device__ float    g_world[NROWS*3];
__device__ float    g_scout[NROWS*3];
__device__ int      g_keep[NROWS];

/* ------------- zero the grid (132.6 MB) ------------- */
__global__ void k_zero() {
    unsigned i = blockIdx.x * blockDim.x + threadIdx.x;
    if (i < NCELL) {
        reinterpret_cast<float4*>(g_grid)[i] = make_float4(0.f, 0.f, 0.f, 0.f);
    }
}

/* ------------- rotation table: XLA-faithful f32 ------------- */
__global__ void k_init_cs() {
    int k = threadIdx.x;
    if (k < 36) {
        float tp   = 6.28318530717958647692f;        /* rounds to f32(2pi) */
        float r36  = __fdiv_rn(1.0f, 36.0f);
        float th   = __fmul_rn(__fmul_rn(tp, (float)k), r36);
        g_cs[2*k]   = cosf(th);
        g_cs[2*k+1] = sinf(th);
    }
}

/* ------------- Hough vote scatter ------------- */
__global__ void k_vote(const float* __restrict__ pc, const float* __restrict__ xyz,
                       const float* __restrict__ scale, const float* __restrict__ prob,
                       const float* __restrict__ corners, int N) {
    int i = blockIdx.x * blockDim.x + threadIdx.x;
    if (i >= N) return;
    const float RCP = __fdiv_rn(1.0f, RESF);
    float px = pc[3*i], py = pc[3*i+1], pz = pc[3*i+2];
    float ox = xyz[3*i], oy = xyz[3*i+1], oz = xyz[3*i+2];
    float w  = prob[i];
    float c0x = corners[0], c0y = corners[1], c0z = corners[2];

    float ty = __fadd_rn(py, oy);
    float fy = __fadd_rn(__fmul_rn(__fsub_rn(ty, c0y), RCP), 0.5f);
    int iy = (int)floorf(fy);
    if (iy < 0 || iy >= GY) return;          /* zero weight for all rots */

    float wsx = __fmul_rn(w, scale[3*i]);
    float wsy = __fmul_rn(w, scale[3*i+1]);
    float wsz = __fmul_rn(w, scale[3*i+2]);

    #pragma unroll 4
    for (int r = 0; r < 36; r++) {
        float cth = g_cs[2*r], sth = g_cs[2*r+1];
        float rx = __fadd_rn(__fmul_rn(ox, cth), __fmul_rn(oz, sth));
        float rz = __fadd_rn(-__fmul_rn(ox, sth), __fmul_rn(oz, cth));
        float tx = __fadd_rn(px, rx);
        float tz = __fadd_rn(pz, rz);
        int ix = (int)floorf(__fadd_rn(__fmul_rn(__fsub_rn(tx, c0x), RCP), 0.5f));
        int iz = (int)floorf(__fadd_rn(__fmul_rn(__fsub_rn(tz, c0z), RCP), 0.5f));
        if (ix >= 0 && ix < GX && iz >= 0 && iz < GZ) {
            unsigned cell = ((unsigned)(ix*GY + iy))*GZ + (unsigned)iz;
            atomicAdd(&g_grid[cell],            w);
            atomicAdd(&g_grid[1u*NCELL + cell], wsx);
            atomicAdd(&g_grid[2u*NCELL + cell], wsy);
            atomicAdd(&g_grid[3u*NCELL + cell], wsz);
        }
    }
}

/* ------------- per-(x,z) max/argmax over y; dist = sqrt(max+1e-7) ------- */
__global__ void k_colmax() {
    int x = blockIdx.x, z = threadIdx.x;
    const float* col = g_grid + (size_t)x * GY * GZ + z;
    float m = col[0]; int my = 0;
    #pragma unroll 8
    for (int y = 1; y < GY; y++) {
        float v = col[(size_t)y * GZ];
        if (v > m) { m = v; my = y; }              /* first index on ties */
    }
    g_dist[x*GZ + z] = sqrtf(__fadd_rn(m, 1e-7f));
    g_yidx[x*GZ + z] = my;
}

/* ------------- deterministic sum of dist (drives only MY filter) ------- */
__global__ void k_sumd() {
    __shared__ float sh[1024];
    float a = 0.f;
    for (int c = threadIdx.x; c < NC2; c += 1024) a += g_dist[c];
    sh[threadIdx.x] = a; __syncthreads();
    for (int o = 512; o > 0; o >>= 1) {
        if (threadIdx.x < o) sh[threadIdx.x] += sh[threadIdx.x + o];
        __syncthreads();
    }
    if (threadIdx.x == 0) g_D = sh[0];
}

/* ------------- per-column: log(dist+1e-30) + raw-bits pass threshold -----
   element can only beat t = D/50 if u > T = exp(-50*d_c/D).
   P(any row's true winner filtered) <= 1024*e^-50 ~ 2e-19.               */
__global__ void k_bth() {
    int c = blockIdx.x * blockDim.x + threadIdx.x;
    if (c >= NC2) return;
    float d = g_dist[c];
    g_logd[c] = logf(__fadd_rn(d, 1e-30f));
    double T = exp(-50.0 * (double)d / (double)g_D);
    long long Mi = (long long)floor(T * 8388608.0) - 64;
    if (Mi < 0) Mi = 0;
    g_bth[c] = ((unsigned)Mi) << 9;
}

/* ------------- Threefry-2x32, key=(0,42) -------------
   parity = 0x1BD11BDA  =>  ks2 = 0x1BD11BDA ^ 42 = 0x1BD11BF0 */
#define TFR(r) { x0 += x1; x1 = __funnelshift_l(x1, x1, r); x1 ^= x0; }

/* partitionable mode: ctr = (hi=0, lo=j); 32-bit output = bits1 ^ bits2 */
__device__ __forceinline__ unsigned tf_bits(unsigned j) {
    unsigned x0 = 0u;                        /* ctr_hi + ks0 (=0)   */
    unsigned x1 = j + 42u;                   /* ctr_lo + ks1        */
    TFR(13) TFR(15) TFR(26) TFR(6)
    x0 += 42u;          x1 += 0x1BD11BF1u;   /* ks1    | ks2+1      */
    TFR(17) TFR(29) TFR(16) TFR(24)
    x0 += 0x1BD11BF0u;  x1 += 2u;            /* ks2    | ks0+2      */
    TFR(13) TFR(15) TFR(26) TFR(6)
    /* x0 += ks0 (=0) */ x1 += 45u;          /* ks0    | ks1+3      */
    TFR(17) TFR(29) TFR(16) TFR(24)
    x0 += 42u;          x1 += 0x1BD11BF4u;   /* ks1    | ks2+4      */
    TFR(13) TFR(15) TFR(26) TFR(6)
    x0 += 0x1BD11BF0u;  x1 += 5u;            /* ks2    | ks0+5      */
    return x0 ^ x1;
}

/* one CTA per row; exact reference score for filter survivors */
__global__ void __launch_bounds__(256) k_cat() {
    __shared__ float ss[256];
    __shared__ int   si[256];
    int r   = blockIdx.x;                    /* 0..1023 */
    int tid = threadIdx.x;
    unsigned base = (unsigned)r * (unsigned)NC2;
    float bs = -3.4e38f;
    int   bi = 0;

    for (int c = tid; c < NC2; c += 256) {
        unsigned b = tf_bits(base + (unsigned)c);
        if (b >= g_bth[c]) {
            unsigned m = b >> 9;
            float u = (m == 0u) ? 1.17549435e-38f
                                : __fadd_rn(__uint_as_float(m | 0x3f800000u), -1.0f);
            float g = -logf(-logf(u));              /* exact ref gumbel */
            float s = __fadd_rn(g_logd[c], g);
            if (s > bs) { bs = s; bi = c; }
        }
    }

    ss[tid] = bs; si[tid] = bi; __syncthreads();
    for (int o = 128; o > 0; o >>= 1) {
        if (tid < o) {
            float s2 = ss[tid+o]; int i2 = si[tid+o];
            if (s2 > ss[tid] || (s2 == ss[tid] && i2 < si[tid])) { ss[tid] = s2; si[tid] = i2; }
        }
        __syncthreads();
    }
    if (tid == 0) g_sample[r] = si[0];
}

/* ------------- gather world loc + scales at sampled cells ------------- */
__global__ void k_gather(const float* __restrict__ corners) {
    int k = blockIdx.x * blockDim.x + threadIdx.x;
    if (k >= NROWS) return;
    int c  = g_sample[k];
    int xi = c / GZ, zi = c - (c / GZ) * GZ;
    int yi = g_yidx[c];
    g_world[3*k+0] = __fadd_rn(__fmul_rn((float)xi, RESF), corners[0]);
    g_world[3*k+1] = __fadd_rn(__fmul_rn((float)yi, RESF), corners[1]);
    g_world[3*k+2] = __fadd_rn(__fmul_rn((float)zi, RESF), corners[2]);
    unsigned cell = ((unsigned)(xi*GY + yi))*GZ + (unsigned)zi;
    float den = __fadd_rn(g_grid[cell], 1e-7f);
    g_scout[3*k+0] = __fdiv_rn(g_grid[1u*NCELL + cell], den);
    g_scout[3*k+1] = __fdiv_rn(g_grid[2u*NCELL + cell], den);
    g_scout[3*k+2] = __fdiv_rn(g_grid[3u*NCELL + cell], den);
}

/* ------------- min distance to seed points ------------- */
__global__ void k_d2seed(const float* __restrict__ vp, int M) {
    __shared__ float sh[128];
    int k = blockIdx.x;
    float wx = g_world[3*k], wy = g_world[3*k+1], wz = g_world[3*k+2];
    float mind = 3.4e38f;
    for (int m = threadIdx.x; m < M; m += 128) {
        float dx = __fsub_rn(wx, vp[3*m]);
        float dy = __fsub_rn(wy, vp[3*m+1]);
        float dz = __fsub_rn(wz, vp[3*m+2]);
        float s  = __fadd_rn(__fadd_rn(__fmul_rn(dx,dx), __fmul_rn(dy,dy)), __fmul_rn(dz,dz));
        float d  = sqrtf(s);
        mind = fminf(mind, d);
    }
    sh[threadIdx.x] = mind; __syncthreads();
    for (int o = 64; o > 0; o >>= 1) {
        if (threadIdx.x < o) sh[threadIdx.x] = fminf(sh[threadIdx.x], sh[threadIdx.x+o]);
        __syncthreads();
    }
    if (threadIdx.x == 0) g_keep[k] = (sh[0] < 0.3f) ? 1 : 0;
}

/* ------------- stable selection + output write ------------- */
__global__ void k_finish(float* __restrict__ out) {
    __shared__ int sel[NPROP];
    if (threadIdx.x == 0) {
        int any = 0;
        for (int k = 0; k < NROWS; k++) any |= g_keep[k];
        int cnt = 0;
        if (any) {
            for (int k = 0; k < NROWS && cnt < NPROP; k++) if (g_keep[k])  sel[cnt++] = k;
            for (int k = 0; k < NROWS && cnt < NPROP; k++) if (!g_keep[k]) sel[cnt++] = k;
        } else {
            for (int k = 0; k < NPROP; k++) sel[cnt++] = k;
        }
    }
    __syncthreads();
    int j = threadIdx.x;
    if (j < NPROP) {
        int k = sel[j];
        out[3*j+0] = g_world[3*k+0];
        out[3*j+1] = g_world[3*k+1];
        out[3*j+2] = g_world[3*k+2];
        out[3*NPROP + j] = 0.0f;
        out[4*NPROP + 3*j+0] = g_scout[3*k+0];
        out[4*NPROP + 3*j+1] = g_scout[3*k+1];
        out[4*NPROP + 3*j+2] = g_scout[3*k+2];
    }
}

extern "C" void kernel_launch(void* const* d_in, const int* in_sizes, int n_in,
                              void* d_out, int out_size) {
    const float* pc      = (const float*)d_in[0];
    const float* xyz     = (const float*)d_in[1];
    const float* scale   = (const float*)d_in[2];
    const float* prob    = (const float*)d_in[3];
    const float* corners = (const float*)d_in[4];
    const float* vp      = (const float*)d_in[5];
    int N = in_sizes[0] / 3;
    int M = in_sizes[5] / 3;
    float* out = (float*)d_out;

    k_zero<<<(NCELL + 255) / 256, 256>>>();
    k_init_cs<<<1, 64>>>();
    k_vote<<<(N + 127) / 128, 128>>>(pc, xyz, scale, prob, corners, N);
    k_colmax<<<GX, GZ>>>();
    k_sumd<<<1, 1024>>>();
    k_bth<<<NC2 / 256, 256>>>();
    k_cat<<<NROWS, 256>>>();
    k_gather<<<4, 256>>>(corners);
    k_d2seed<<<NROWS, 128>>>(vp, M);
    k_finish<<<1, 256>>>(out);
}

// round 7
// speedup vs baseline: 1.0711x; 1.0711x over previous
#include <cuda_runtime.h>
#include <math.h>
#include <stdint.h>

#define GX 272
#define GY 112
#define GZ 272
#define NCELL 8286208u            /* GX*GY*GZ */
#define NC2   73984u              /* GX*GZ = 289*256 */
#define NROWS 1024
#define NPROP 256
#define RESF  0.03f

#define NBITS 75759616u           /* NROWS * NC2 */
#define BITS_BLK_WORK 8192u       /* counters per bits-block (256 thr * 32) */
#define BB1 3083u                 /* bits blocks in fused kernel 1 */
#define BB2 3083u                 /* bits blocks in fused kernel 2 */
#define BB3 3082u                 /* bits blocks in fused kernel 3 (3083+3083+3082 = 9248 = NBITS/8192) */
#define ZBLK_OBJ 8092u            /* NCELL/4/256 */
#define ZBLK_GSC 24276u           /* 3*NCELL/4/256 */
#define ZBLKS (ZBLK_OBJ + ZBLK_GSC)
#define CMBLKS 289u               /* NC2/256 */

/* ------------- static device scratch (no allocations) ------------- */
__device__ float    g_obj[NCELL];        /*  33 MB: objectness plane   */
__device__ float    g_gsc[3u*NCELL];     /*  99 MB: scales, cell*3+ch  */
__device__ unsigned g_bits[NBITS];       /* 303 MB: precomputed RNG    */
__device__ float    g_cs[72];
__device__ float    g_dist[NC2];
__device__ float    g_logd[NC2];
__device__ int      g_yidx[NC2];
__device__ unsigned g_bth[NC2];
__device__ float    g_D;
__device__ float    g_world[NROWS*3];
__device__ float    g_scout[NROWS*3];
__device__ int      g_keep[NROWS];

/* ------------- Threefry-2x32, key=(0,42) -------------
   parity = 0x1BD11BDA  =>  ks2 = 0x1BD11BDA ^ 42 = 0x1BD11BF0
   partitionable mode: ctr = (hi=0, lo=j); 32-bit out = bits1 ^ bits2
   *** verified bit-exact in round 6 — do not touch ***              */
#define TFR(r) { x0 += x1; x1 = __funnelshift_l(x1, x1, r); x1 ^= x0; }

__device__ __forceinline__ unsigned tf_bits(unsigned j) {
    unsigned x0 = 0u;                        /* ctr_hi + ks0 (=0)   */
    unsigned x1 = j + 42u;                   /* ctr_lo + ks1        */
    TFR(13) TFR(15) TFR(26) TFR(6)
    x0 += 42u;          x1 += 0x1BD11BF1u;   /* ks1    | ks2+1      */
    TFR(17) TFR(29) TFR(16) TFR(24)
    x0 += 0x1BD11BF0u;  x1 += 2u;            /* ks2    | ks0+2      */
    TFR(13) TFR(15) TFR(26) TFR(6)
    /* x0 += ks0 (=0) */ x1 += 45u;          /* ks0    | ks1+3      */
    TFR(17) TFR(29) TFR(16) TFR(24)
    x0 += 42u;          x1 += 0x1BD11BF4u;   /* ks1    | ks2+4      */
    TFR(13) TFR(15) TFR(26) TFR(6)
    x0 += 0x1BD11BF0u;  x1 += 5u;            /* ks2    | ks0+5      */
    return x0 ^ x1;
}

/* bits block: 256 threads produce 8192 consecutive counters, coalesced */
__device__ __forceinline__ void bits_job(unsigned blk, unsigned t) {
    unsigned base = blk * BITS_BLK_WORK;
    #pragma unroll 4
    for (unsigned k = 0; k < 32; k++) {
        unsigned idx = base + (k << 8) + t;
        g_bits[idx] = tf_bits(idx);
    }
}

/* ============ K1: bits chunk 1  ||  zero grid  ||  cos/sin table ============ */
__global__ void __launch_bounds__(256) k_f1() {
    unsigned b = blockIdx.x, t = threadIdx.x;
    if (b < BB1) {
        if (b == 0 && t < 36) {
            float tp  = 6.28318530717958647692f;     /* rounds to f32(2pi) */
            float r36 = __fdiv_rn(1.0f, 36.0f);
            float th  = __fmul_rn(__fmul_rn(tp, (float)t), r36);
            g_cs[2*t]   = cosf(th);
            g_cs[2*t+1] = sinf(th);
        }
        bits_job(b, t);
    } else {
        unsigned zb = b - BB1;
        float4 z4 = make_float4(0.f, 0.f, 0.f, 0.f);
        if (zb < ZBLK_OBJ)
            reinterpret_cast<float4*>(g_obj)[zb*256u + t] = z4;
        else
            reinterpret_cast<float4*>(g_gsc)[(zb - ZBLK_OBJ)*256u + t] = z4;
    }
}

/* ============ K2: bits chunk 2  ||  Hough vote scatter ============ */
__global__ void __launch_bounds__(256) k_f2(const float* __restrict__ pc,
                                            const float* __restrict__ xyz,
                                            const float* __restrict__ scale,
                                            const float* __restrict__ prob,
                                            const float* __restrict__ corners, int N) {
    unsigned b = blockIdx.x, t = threadIdx.x;
    if (b < BB2) {
        if (b == 0 && t == 0) g_D = 0.0f;
        bits_job(BB1 + b, t);
        return;
    }
    int i = (int)(b - BB2) * 256 + (int)t;
    if (i >= N) return;
    const float RCP = __fdiv_rn(1.0f, RESF);
    float px = pc[3*i], py = pc[3*i+1], pz = pc[3*i+2];
    float ox = xyz[3*i], oy = xyz[3*i+1], oz = xyz[3*i+2];
    float w  = prob[i];
    float c0x = corners[0], c0y = corners[1], c0z = corners[2];

    float ty = __fadd_rn(py, oy);
    float fy = __fadd_rn(__fmul_rn(__fsub_rn(ty, c0y), RCP), 0.5f);
    int iy = (int)floorf(fy);
    if (iy < 0 || iy >= GY) return;          /* zero weight for all rots */

    float wsx = __fmul_rn(w, scale[3*i]);
    float wsy = __fmul_rn(w, scale[3*i+1]);
    float wsz = __fmul_rn(w, scale[3*i+2]);

    #pragma unroll 4
    for (int r = 0; r < 36; r++) {
        float cth = g_cs[2*r], sth = g_cs[2*r+1];
        float rx = __fadd_rn(__fmul_rn(ox, cth), __fmul_rn(oz, sth));
        float rz = __fadd_rn(-__fmul_rn(ox, sth), __fmul_rn(oz, cth));
        float tx = __fadd_rn(px, rx);
        float tz = __fadd_rn(pz, rz);
        int ix = (int)floorf(__fadd_rn(__fmul_rn(__fsub_rn(tx, c0x), RCP), 0.5f));
        int iz = (int)floorf(__fadd_rn(__fmul_rn(__fsub_rn(tz, c0z), RCP), 0.5f));
        if (ix >= 0 && ix < GX && iz >= 0 && iz < GZ) {
            unsigned cell = ((unsigned)(ix*GY + iy))*GZ + (unsigned)iz;
            atomicAdd(&g_obj[cell],        w);
            atomicAdd(&g_gsc[cell*3u],     wsx);
            atomicAdd(&g_gsc[cell*3u+1u],  wsy);
            atomicAdd(&g_gsc[cell*3u+2u],  wsz);
        }
    }
}

/* ============ K3: bits chunk 3  ||  colmax + dist + sum(dist) ============ */
__global__ void __launch_bounds__(256) k_f3() {
    __shared__ float sh[256];
    unsigned b = blockIdx.x, t = threadIdx.x;
    if (b < BB3) { bits_job(BB1 + BB2 + b, t); return; }

    unsigned cell = (b - BB3) * 256u + t;          /* < NC2 exactly */
    unsigned x = cell / GZ, z = cell - x * GZ;
    const float* col = g_obj + (size_t)x * GY * GZ + z;
    float m = col[0]; int my = 0;
    #pragma unroll 8
    for (int y = 1; y < GY; y++) {
        float v = col[(size_t)y * GZ];
        if (v > m) { m = v; my = y; }              /* first index on ties */
    }
    float d = sqrtf(__fadd_rn(m, 1e-7f));          /* XLA pow(x,.5)->sqrt */
    g_dist[cell] = d;
    g_yidx[cell] = my;

    /* block partial sum of dist -> g_D (order-nondeterministic; only feeds
       the conservative filter threshold, never the output values) */
    sh[t] = d; __syncthreads();
    for (int o = 128; o > 0; o >>= 1) {
        if (t < (unsigned)o) sh[t] += sh[t + o];
        __syncthreads();
    }
    if (t == 0) atomicAdd(&g_D, sh[0]);
}

/* ============ K4: log(dist) + raw-bits pass threshold ============
   element can only beat s_T = D/50 if u > T = exp(-50*d_c/D).
   P(any row's true winner filtered) <= 1024*e^-50 ~ 2e-19.        */
__global__ void __launch_bounds__(256) k_bth() {
    unsigned c = blockIdx.x * 256u + threadIdx.x;
    if (c >= NC2) return;
    float d = g_dist[c];
    g_logd[c] = logf(__fadd_rn(d, 1e-30f));
    double T = exp(-50.0 * (double)d / (double)g_D);
    long long Mi = (long long)floor(T * 8388608.0) - 64;
    if (Mi < 0) Mi = 0;
    g_bth[c] = ((unsigned)Mi) << 9;
}

/* ============ K5: per-row select (stream bits) + gather + seed dist ============ */
__device__ __forceinline__ void sel_try(unsigned b, unsigned th, int c,
                                        float& bs, int& bi) {
    if (b >= th) {
        unsigned m = b >> 9;
        float u = (m == 0u) ? 1.17549435e-38f
                            : __fadd_rn(__uint_as_float(m | 0x3f800000u), -1.0f);
        float g = -logf(-logf(u));                 /* exact ref gumbel */
        float s = __fadd_rn(g_logd[c], g);
        if (s > bs) { bs = s; bi = c; }
    }
}

__global__ void __launch_bounds__(256) k_sel(const float* __restrict__ corners,
                                             const float* __restrict__ vp, int M) {
    __shared__ float ss[256];
    __shared__ int   si[256];
    __shared__ float sw[3];
    int r = blockIdx.x, tid = threadIdx.x;
    const uint4* rowb = reinterpret_cast<const uint4*>(g_bits + (size_t)r * NC2);
    const uint4* thv  = reinterpret_cast<const uint4*>(g_bth);
    float bs = -3.4e38f; int bi = 0;

    for (unsigned q = tid; q < NC2/4u; q += 256u) {
        uint4 v  = rowb[q];
        uint4 th = thv[q];
        int c = (int)(q * 4u);
        sel_try(v.x, th.x, c,   bs, bi);
        sel_try(v.y, th.y, c+1, bs, bi);
        sel_try(v.z, th.z, c+2, bs, bi);
        sel_try(v.w, th.w, c+3, bs, bi);
    }

    ss[tid] = bs; si[tid] = bi; __syncthreads();
    for (int o = 128; o > 0; o >>= 1) {
        if (tid < o) {
            float s2 = ss[tid+o]; int i2 = si[tid+o];
            if (s2 > ss[tid] || (s2 == ss[tid] && i2 < si[tid])) { ss[tid] = s2; si[tid] = i2; }
        }
        __syncthreads();
    }

    if (tid == 0) {
        int c  = si[0];
        int xi = c / GZ, zi = c - (c / GZ) * GZ;
        int yi = g_yidx[c];
        float wx = __fadd_rn(__fmul_rn((float)xi, RESF), corners[0]);
        float wy = __fadd_rn(__fmul_rn((float)yi, RESF), corners[1]);
        float wz = __fadd_rn(__fmul_rn((float)zi, RESF), corners[2]);
        g_world[3*r+0] = wx; g_world[3*r+1] = wy; g_world[3*r+2] = wz;
        sw[0] = wx; sw[1] = wy; sw[2] = wz;
        unsigned cell = ((unsigned)(xi*GY + yi))*GZ + (unsigned)zi;
        float den = __fadd_rn(g_obj[cell], 1e-7f);
        g_scout[3*r+0] = __fdiv_rn(g_gsc[cell*3u],    den);
        g_scout[3*r+1] = __fdiv_rn(g_gsc[cell*3u+1u], den);
        g_scout[3*r+2] = __fdiv_rn(g_gsc[cell*3u+2u], den);
    }
    __syncthreads();

    /* min distance to seed points for this row */
    float wx = sw[0], wy = sw[1], wz = sw[2];
    float mind = 3.4e38f;
    for (int m = tid; m < M; m += 256) {
        float dx = __fsub_rn(wx, vp[3*m]);
        float dy = __fsub_rn(wy, vp[3*m+1]);
        float dz = __fsub_rn(wz, vp[3*m+2]);
        float s  = __fadd_rn(__fadd_rn(__fmul_rn(dx,dx), __fmul_rn(dy,dy)), __fmul_rn(dz,dz));
        mind = fminf(mind, sqrtf(s));
    }
    ss[tid] = mind; __syncthreads();
    for (int o = 128; o > 0; o >>= 1) {
        if (tid < o) ss[tid] = fminf(ss[tid], ss[tid+o]);
        __syncthreads();
    }
    if (tid == 0) g_keep[r] = (ss[0] < 0.3f) ? 1 : 0;
}

/* ============ K6: stable selection + output write ============ */
__global__ void k_finish(float* __restrict__ out) {
    __shared__ int sel[NPROP];
    if (threadIdx.x == 0) {
        int any = 0;
        for (int k = 0; k < NROWS; k++) any |= g_keep[k];
        int cnt = 0;
        if (any) {
            for (int k = 0; k < NROWS && cnt < NPROP; k++) if (g_keep[k])  sel[cnt++] = k;
            for (int k = 0; k < NROWS && cnt < NPROP; k++) if (!g_keep[k]) sel[cnt++] = k;
        } else {
            for (int k = 0; k < NPROP; k++) sel[cnt++] = k;
        }
    }
    __syncthreads();
    int j = threadIdx.x;
    if (j < NPROP) {
        int k = sel[j];
        out[3*j+0] = g_world[3*k+0];
        out[3*j+1] = g_world[3*k+1];
        out[3*j+2] = g_world[3*k+2];
        out[3*NPROP + j] = 0.0f;
        out[4*NPROP + 3*j+0] = g_scout[3*k+0];
        out[4*NPROP + 3*j+1] = g_scout[3*k+1];
        out[4*NPROP + 3*j+2] = g_scout[3*k+2];
    }
}

extern "C" void kernel_launch(void* const* d_in, const int* in_sizes, int n_in,
                              void* d_out, int out_size) {
    const float* pc      = (const float*)d_in[0];
    const float* xyz     = (const float*)d_in[1];
    const float* scale   = (const float*)d_in[2];
    const float* prob    = (const float*)d_in[3];
    const float* corners = (const float*)d_in[4];
    const float* vp      = (const float*)d_in[5];
    int N = in_sizes[0] / 3;
    int M = in_sizes[5] / 3;
    float* out = (float*)d_out;
    int vb = (N + 255) / 256;

    k_f1<<<BB1 + ZBLKS, 256>>>();
    k_f2<<<BB2 + vb, 256>>>(pc, xyz, scale, prob, corners, N);
    k_f3<<<BB3 + CMBLKS, 256>>>();
    k_bth<<<CMBLKS, 256>>>();
    k_sel<<<NROWS, 256>>>(corners, vp, M);
    k_finish<<<1, 256>>>(out);
}

// round 8
// speedup vs baseline: 1.1897x; 1.1107x over previous
#include <cuda_runtime.h>
#include <math.h>
#include <stdint.h>

#define GX 272
#define GY 112
#define GZ 272
#define NCELL 8286208u            /* GX*GY*GZ */
#define NC2   73984u              /* GX*GZ = 289*256 */
#define NROWS 1024
#define NPROP 256
#define RESF  0.03f

#define RPRE  320u                /* rows with precomputed bits */
#define NPREW (RPRE*NC2)          /* 23,674,880 = 8192*2890 */
#define BWORK 8192u               /* counters per bits-block (256 thr * 32) */
#define PB1   900u                /* bits blocks fused into K1 */
#define PB2   1700u               /* bits blocks fused into K2 */
#define PB3   290u                /* bits blocks fused into K3 (900+1700+290 = 2890) */
#define ZBLKS 32368u              /* NCELL/256 float4-zero blocks */
#define CMBLKS 289u               /* NC2/256 */

/* ------------- static device scratch (no allocations) ------------- */
__device__ float4   g_grid4[NCELL];      /* 132 MB: (obj, sx, sy, sz) per cell */
__device__ unsigned g_bits[NPREW];       /*  95 MB: precomputed RNG rows 0..319 */
__device__ float    g_cs[72];
__device__ float    g_dist[NC2];
__device__ float    g_logd[NC2];
__device__ int      g_yidx[NC2];
__device__ unsigned g_bth[NC2];
__device__ float    g_D;
__device__ float    g_world[NROWS*3];
__device__ float    g_scout[NROWS*3];
__device__ int      g_keep[NROWS];

/* ------------- Threefry-2x32, key=(0,42) -------------
   parity = 0x1BD11BDA  =>  ks2 = 0x1BD11BDA ^ 42 = 0x1BD11BF0
   partitionable mode: ctr = (hi=0, lo=j); 32-bit out = bits1 ^ bits2
   *** verified bit-exact in round 6 — do not touch ***              */
#define TFR(r) { x0 += x1; x1 = __funnelshift_l(x1, x1, r); x1 ^= x0; }

__device__ __forceinline__ unsigned tf_bits(unsigned j) {
    unsigned x0 = 0u;                        /* ctr_hi + ks0 (=0)   */
    unsigned x1 = j + 42u;                   /* ctr_lo + ks1        */
    TFR(13) TFR(15) TFR(26) TFR(6)
    x0 += 42u;          x1 += 0x1BD11BF1u;   /* ks1    | ks2+1      */
    TFR(17) TFR(29) TFR(16) TFR(24)
    x0 += 0x1BD11BF0u;  x1 += 2u;            /* ks2    | ks0+2      */
    TFR(13) TFR(15) TFR(26) TFR(6)
    /* x0 += ks0 (=0) */ x1 += 45u;          /* ks0    | ks1+3      */
    TFR(17) TFR(29) TFR(16) TFR(24)
    x0 += 42u;          x1 += 0x1BD11BF4u;   /* ks1    | ks2+4      */
    TFR(13) TFR(15) TFR(26) TFR(6)
    x0 += 0x1BD11BF0u;  x1 += 5u;            /* ks2    | ks0+5      */
    return x0 ^ x1;
}

/* bits block: 256 threads produce 8192 consecutive counters, coalesced */
__device__ __forceinline__ void bits_job(unsigned blk, unsigned t) {
    unsigned base = blk * BWORK;
    #pragma unroll 4
    for (unsigned k = 0; k < 32; k++) {
        unsigned idx = base + (k << 8) + t;
        g_bits[idx] = tf_bits(idx);
    }
}

/* ============ K1: bits chunk 1  ||  zero grid  ||  cos/sin table ============ */
__global__ void __launch_bounds__(256) k_f1() {
    unsigned b = blockIdx.x, t = threadIdx.x;
    if (b < PB1) {
        if (b == 0) {
            if (t < 36) {
                float tp  = 6.28318530717958647692f;     /* rounds to f32(2pi) */
                float r36 = __fdiv_rn(1.0f, 36.0f);
                float th  = __fmul_rn(__fmul_rn(tp, (float)t), r36);
                g_cs[2*t]   = cosf(th);
                g_cs[2*t+1] = sinf(th);
            }
            if (t == 0) g_D = 0.0f;
        }
        bits_job(b, t);
    } else {
        unsigned zb = b - PB1;
        g_grid4[zb*256u + t] = make_float4(0.f, 0.f, 0.f, 0.f);
    }
}

/* ============ K2: Hough vote scatter (v4 red)  ||  bits chunk 2 ============ */
__global__ void __launch_bounds__(256) k_f2(const float* __restrict__ pc,
                                            const float* __restrict__ xyz,
                                            const float* __restrict__ scale,
                                            const float* __restrict__ prob,
                                            const float* __restrict__ corners,
                                            int N, int vb) {
    unsigned b = blockIdx.x, t = threadIdx.x;
    if (b >= (unsigned)vb) { bits_job(PB1 + (b - vb), t); return; }

    int i = (int)b * 256 + (int)t;
    if (i >= N) return;
    const float RCP = __fdiv_rn(1.0f, RESF);
    float px = pc[3*i], py = pc[3*i+1], pz = pc[3*i+2];
    float ox = xyz[3*i], oy = xyz[3*i+1], oz = xyz[3*i+2];
    float w  = prob[i];
    float c0x = corners[0], c0y = corners[1], c0z = corners[2];

    float ty = __fadd_rn(py, oy);
    float fy = __fadd_rn(__fmul_rn(__fsub_rn(ty, c0y), RCP), 0.5f);
    int iy = (int)floorf(fy);
    if (iy < 0 || iy >= GY) return;          /* zero weight for all rots */

    float wsx = __fmul_rn(w, scale[3*i]);
    float wsy = __fmul_rn(w, scale[3*i+1]);
    float wsz = __fmul_rn(w, scale[3*i+2]);

    #pragma unroll 4
    for (int r = 0; r < 36; r++) {
        float cth = g_cs[2*r], sth = g_cs[2*r+1];
        float rx = __fadd_rn(__fmul_rn(ox, cth), __fmul_rn(oz, sth));
        float rz = __fadd_rn(-__fmul_rn(ox, sth), __fmul_rn(oz, cth));
        float tx = __fadd_rn(px, rx);
        float tz = __fadd_rn(pz, rz);
        int ix = (int)floorf(__fadd_rn(__fmul_rn(__fsub_rn(tx, c0x), RCP), 0.5f));
        int iz = (int)floorf(__fadd_rn(__fmul_rn(__fsub_rn(tz, c0z), RCP), 0.5f));
        if (ix >= 0 && ix < GX && iz >= 0 && iz < GZ) {
            unsigned cell = ((unsigned)(ix*GY + iy))*GZ + (unsigned)iz;
            asm volatile("red.global.add.v4.f32 [%0], {%1, %2, %3, %4};"
                         :: "l"(&g_grid4[cell]), "f"(w), "f"(wsx), "f"(wsy), "f"(wsz)
                         : "memory");
        }
    }
}

/* ============ K3: colmax + dist + sum(dist)  ||  bits chunk 3 ============ */
__global__ void __launch_bounds__(256) k_f3() {
    __shared__ float sh[256];
    unsigned b = blockIdx.x, t = threadIdx.x;
    if (b >= CMBLKS) { bits_job(PB1 + PB2 + (b - CMBLKS), t); return; }

    unsigned cell = b * 256u + t;                  /* < NC2 exactly */
    unsigned x = cell / GZ, z = cell - x * GZ;
    const float4* col = g_grid4 + (size_t)x * GY * GZ + z;
    float m = col[0].x; int my = 0;
    #pragma unroll 8
    for (int y = 1; y < GY; y++) {
        float v = col[(size_t)y * GZ].x;
        if (v > m) { m = v; my = y; }              /* first index on ties */
    }
    float d = sqrtf(__fadd_rn(m, 1e-7f));          /* XLA pow(x,.5)->sqrt */
    g_dist[cell] = d;
    g_yidx[cell] = my;

    /* block partial sum of dist -> g_D (feeds only the conservative filter) */
    sh[t] = d; __syncthreads();
    for (int o = 128; o > 0; o >>= 1) {
        if (t < (unsigned)o) sh[t] += sh[t + o];
        __syncthreads();
    }
    if (t == 0) atomicAdd(&g_D, sh[0]);
}

/* ============ K4: log(dist) + raw-bits pass threshold (f32) ============
   element can only beat s_T = D/50 if u > T = exp(-50*d_c/D).
   margin 512 mantissa units >> __expf error (~tens of units).         */
__global__ void __launch_bounds__(256) k_bth() {
    unsigned c = blockIdx.x * 256u + threadIdx.x;
    if (c >= NC2) return;
    float d = g_dist[c];
    g_logd[c] = logf(__fadd_rn(d, 1e-30f));
    float T = __expf(-50.0f * d / g_D);
    int Mi = (int)floorf(T * 8388608.0f) - 512;
    if (Mi < 0) Mi = 0;
    g_bth[c] = ((unsigned)Mi) << 9;
}

/* ============ K5: per-row select + gather + seed dist ============ */
__device__ __forceinline__ void sel_try(unsigned b, unsigned th, int c,
                                        float& bs, int& bi) {
    if (b >= th) {
        unsigned m = b >> 9;
        float u = (m == 0u) ? 1.17549435e-38f
                            : __fadd_rn(__uint_as_float(m | 0x3f800000u), -1.0f);
        float g = -logf(-logf(u));                 /* exact ref gumbel */
        float s = __fadd_rn(g_logd[c], g);
        if (s > bs) { bs = s; bi = c; }
    }
}

__global__ void __launch_bounds__(256) k_sel(const float* __restrict__ corners,
                                             const float* __restrict__ vp, int M) {
    __shared__ float ss[256];
    __shared__ int   si[256];
    __shared__ float sw[3];
    int r = blockIdx.x, tid = threadIdx.x;
    float bs = -3.4e38f; int bi = 0;

    if (r < (int)RPRE) {
        /* precomputed rows: stream bits from DRAM, vectorized */
        const uint4* rowb = reinterpret_cast<const uint4*>(g_bits + (size_t)r * NC2);
        const uint4* thv  = reinterpret_cast<const uint4*>(g_bth);
        for (unsigned q = tid; q < NC2/4u; q += 256u) {
            uint4 v  = rowb[q];
            uint4 th = thv[q];
            int c = (int)(q * 4u);
            sel_try(v.x, th.x, c,   bs, bi);
            sel_try(v.y, th.y, c+1, bs, bi);
            sel_try(v.z, th.z, c+2, bs, bi);
            sel_try(v.w, th.w, c+3, bs, bi);
        }
    } else {
        /* inline threefry rows: pure ALU, no staging traffic */
        unsigned base = (unsigned)r * NC2;
        for (unsigned c = tid; c < NC2; c += 256u) {
            unsigned b = tf_bits(base + c);
            if (b >= g_bth[c]) sel_try(b, 0u, (int)c, bs, bi);
        }
    }

    ss[tid] = bs; si[tid] = bi; __syncthreads();
    for (int o = 128; o > 0; o >>= 1) {
        if (tid < o) {
            float s2 = ss[tid+o]; int i2 = si[tid+o];
            if (s2 > ss[tid] || (s2 == ss[tid] && i2 < si[tid])) { ss[tid] = s2; si[tid] = i2; }
        }
        __syncthreads();
    }

    if (tid == 0) {
        int c  = si[0];
        int xi = c / GZ, zi = c - (c / GZ) * GZ;
        int yi = g_yidx[c];
        float wx = __fadd_rn(__fmul_rn((float)xi, RESF), corners[0]);
        float wy = __fadd_rn(__fmul_rn((float)yi, RESF), corners[1]);
        float wz = __fadd_rn(__fmul_rn((float)zi, RESF), corners[2]);
        g_world[3*r+0] = wx; g_world[3*r+1] = wy; g_world[3*r+2] = wz;
        sw[0] = wx; sw[1] = wy; sw[2] = wz;
        unsigned cell = ((unsigned)(xi*GY + yi))*GZ + (unsigned)zi;
        float4 gv = g_grid4[cell];
        float den = __fadd_rn(gv.x, 1e-7f);
        g_scout[3*r+0] = __fdiv_rn(gv.y, den);
        g_scout[3*r+1] = __fdiv_rn(gv.z, den);
        g_scout[3*r+2] = __fdiv_rn(gv.w, den);
    }
    __syncthreads();

    /* min distance to seed points for this row */
    float wx = sw[0], wy = sw[1], wz = sw[2];
    float mind = 3.4e38f;
    for (int m = tid; m < M; m += 256) {
        float dx = __fsub_rn(wx, vp[3*m]);
        float dy = __fsub_rn(wy, vp[3*m+1]);
        float dz = __fsub_rn(wz, vp[3*m+2]);
        float s  = __fadd_rn(__fadd_rn(__fmul_rn(dx,dx), __fmul_rn(dy,dy)), __fmul_rn(dz,dz));
        mind = fminf(mind, sqrtf(s));
    }
    ss[tid] = mind; __syncthreads();
    for (int o = 128; o > 0; o >>= 1) {
        if (tid < o) ss[tid] = fminf(ss[tid], ss[tid+o]);
        __syncthreads();
    }
    if (tid == 0) g_keep[r] = (ss[0] < 0.3f) ? 1 : 0;
}

/* ============ K6: stable selection + output write ============ */
__global__ void k_finish(float* __restrict__ out) {
    __shared__ int sel[NPROP];
    if (threadIdx.x == 0) {
        int any = 0;
        for (int k = 0; k < NROWS; k++) any |= g_keep[k];
        int cnt = 0;
        if (any) {
            for (int k = 0; k < NROWS && cnt < NPROP; k++) if (g_keep[k])  sel[cnt++] = k;
            for (int k = 0; k < NROWS && cnt < NPROP; k++) if (!g_keep[k]) sel[cnt++] = k;
        } else {
            for (int k = 0; k < NPROP; k++) sel[cnt++] = k;
        }
    }
    __syncthreads();
    int j = threadIdx.x;
    if (j < NPROP) {
        int k = sel[j];
        out[3*j+0] = g_world[3*k+0];
        out[3*j+1] = g_world[3*k+1];
        out[3*j+2] = g_world[3*k+2];
        out[3*NPROP + j] = 0.0f;
        out[4*NPROP + 3*j+0] = g_scout[3*k+0];
        out[4*NPROP + 3*j+1] = g_scout[3*k+1];
        out[4*NPROP + 3*j+2] = g_scout[3*k+2];
    }
}

extern "C" void kernel_launch(void* const* d_in, const int* in_sizes, int n_in,
                              void* d_out, int out_size) {
    const float* pc      = (const float*)d_in[0];
    const float* xyz     = (const float*)d_in[1];
    const float* scale   = (const float*)d_in[2];
    const float* prob    = (const float*)d_in[3];
    const float* corners = (const float*)d_in[4];
    const float* vp      = (const float*)d_in[5];
    int N = in_sizes[0] / 3;
    int M = in_sizes[5] / 3;
    float* out = (float*)d_out;
    int vb = (N + 255) / 256;

    k_f1<<<PB1 + ZBLKS, 256>>>();
    k_f2<<<vb + PB2, 256>>>(pc, xyz, scale, prob, corners, N, vb);
    k_f3<<<CMBLKS + PB3, 256>>>();
    k_bth<<<CMBLKS, 256>>>();
    k_sel<<<NROWS, 256>>>(corners, vp, M);
    k_finish<<<1, 256>>>(out);
}

// round 9
// speedup vs baseline: 1.2617x; 1.0605x over previous
#include <cuda_runtime.h>
#include <math.h>
#include <stdint.h>

#define GX 272
#define GY 112
#define GZ 272
#define NCELL 8286208u            /* GX*GY*GZ */
#define NC2   73984u              /* GX*GZ = 289*256 */
#define NROWS 1024
#define NPROP 256
#define RESF  0.03f

#define RPRE  448u                /* rows with precomputed bits */
#define NPREW (RPRE*NC2)          /* 33,144,832 = 8192*4046 */
#define BWORK 8192u               /* counters per bits-block (256 thr * 32) */
#define PB1   1040u               /* bits blocks fused into K1 */
#define PB2   2200u               /* bits blocks fused into K2 */
#define PB3   806u                /* bits blocks fused into K3 (sum = 4046) */
#define ZBLKS 32368u              /* NCELL/256 float4-zero blocks */
#define CMBLKS 289u               /* NC2/256 */

/* ------------- static device scratch (no allocations) ------------- */
__device__ float4   g_grid4[NCELL];      /* 132 MB: (obj, sx, sy, sz) per cell */
__device__ unsigned g_bits[NPREW];       /* 133 MB: precomputed RNG rows 0..447 */
__device__ float    g_cs[72];
__device__ float    g_dist[NC2];
__device__ float    g_logd[NC2];
__device__ int      g_yidx[NC2];
__device__ unsigned g_bth[NC2];
__device__ float    g_D;
__device__ float    g_world[NROWS*3];
__device__ float    g_scout[NROWS*3];
__device__ int      g_keep[NROWS];

/* ------------- Threefry-2x32, key=(0,42) -------------
   parity = 0x1BD11BDA  =>  ks2 = 0x1BD11BDA ^ 42 = 0x1BD11BF0
   partitionable mode: ctr = (hi=0, lo=j); 32-bit out = bits1 ^ bits2
   *** verified bit-exact in round 6 — do not touch ***              */
#define TFR(r) { x0 += x1; x1 = __funnelshift_l(x1, x1, r); x1 ^= x0; }

__device__ __forceinline__ unsigned tf_bits(unsigned j) {
    unsigned x0 = 0u;                        /* ctr_hi + ks0 (=0)   */
    unsigned x1 = j + 42u;                   /* ctr_lo + ks1        */
    TFR(13) TFR(15) TFR(26) TFR(6)
    x0 += 42u;          x1 += 0x1BD11BF1u;   /* ks1    | ks2+1      */
    TFR(17) TFR(29) TFR(16) TFR(24)
    x0 += 0x1BD11BF0u;  x1 += 2u;            /* ks2    | ks0+2      */
    TFR(13) TFR(15) TFR(26) TFR(6)
    /* x0 += ks0 (=0) */ x1 += 45u;          /* ks0    | ks1+3      */
    TFR(17) TFR(29) TFR(16) TFR(24)
    x0 += 42u;          x1 += 0x1BD11BF4u;   /* ks1    | ks2+4      */
    TFR(13) TFR(15) TFR(26) TFR(6)
    x0 += 0x1BD11BF0u;  x1 += 5u;            /* ks2    | ks0+5      */
    return x0 ^ x1;
}

/* 4 independent threefry chains, interleaved for ILP */
#define TFR4(r) { a0 += a1; b0 += b1; c0 += c1; d0 += d1;              \
                  a1 = __funnelshift_l(a1, a1, r); b1 = __funnelshift_l(b1, b1, r); \
                  c1 = __funnelshift_l(c1, c1, r); d1 = __funnelshift_l(d1, d1, r); \
                  a1 ^= a0; b1 ^= b0; c1 ^= c0; d1 ^= d0; }
#define INJ4(k0v, k1v) { a0 += k0v; b0 += k0v; c0 += k0v; d0 += k0v;   \
                         a1 += k1v; b1 += k1v; c1 += k1v; d1 += k1v; }

__device__ __forceinline__ void tf_bits4(unsigned j0, unsigned j1, unsigned j2, unsigned j3,
                                         unsigned& o0, unsigned& o1, unsigned& o2, unsigned& o3) {
    unsigned a0 = 0u, a1 = j0 + 42u;
    unsigned b0 = 0u, b1 = j1 + 42u;
    unsigned c0 = 0u, c1 = j2 + 42u;
    unsigned d0 = 0u, d1 = j3 + 42u;
    TFR4(13) TFR4(15) TFR4(26) TFR4(6)
    INJ4(42u, 0x1BD11BF1u)
    TFR4(17) TFR4(29) TFR4(16) TFR4(24)
    INJ4(0x1BD11BF0u, 2u)
    TFR4(13) TFR4(15) TFR4(26) TFR4(6)
    INJ4(0u, 45u)
    TFR4(17) TFR4(29) TFR4(16) TFR4(24)
    INJ4(42u, 0x1BD11BF4u)
    TFR4(13) TFR4(15) TFR4(26) TFR4(6)
    INJ4(0x1BD11BF0u, 5u)
    o0 = a0 ^ a1; o1 = b0 ^ b1; o2 = c0 ^ c1; o3 = d0 ^ d1;
}

/* bits block: 256 threads produce 8192 consecutive counters, coalesced */
__device__ __forceinline__ void bits_job(unsigned blk, unsigned t) {
    unsigned base = blk * BWORK;
    #pragma unroll
    for (unsigned k = 0; k < 32; k += 4) {
        unsigned i0 = base + (k << 8) + t;
        unsigned o0, o1, o2, o3;
        tf_bits4(i0, i0 + 256u, i0 + 512u, i0 + 768u, o0, o1, o2, o3);
        g_bits[i0]        = o0;
        g_bits[i0 + 256u] = o1;
        g_bits[i0 + 512u] = o2;
        g_bits[i0 + 768u] = o3;
    }
}

/* ============ K1: bits chunk 1  ||  zero grid  ||  cos/sin table ============ */
__global__ void __launch_bounds__(256) k_f1() {
    unsigned b = blockIdx.x, t = threadIdx.x;
    if (b < PB1) {
        if (b == 0) {
            if (t < 36) {
                float tp  = 6.28318530717958647692f;     /* rounds to f32(2pi) */
                float r36 = __fdiv_rn(1.0f, 36.0f);
                float th  = __fmul_rn(__fmul_rn(tp, (float)t), r36);
                g_cs[2*t]   = cosf(th);
                g_cs[2*t+1] = sinf(th);
            }
            if (t == 0) g_D = 0.0f;
        }
        bits_job(b, t);
    } else {
        unsigned zb = b - PB1;
        g_grid4[zb*256u + t] = make_float4(0.f, 0.f, 0.f, 0.f);
    }
}

/* ============ K2: Hough vote scatter (v4 red)  ||  bits chunk 2 ============ */
__global__ void __launch_bounds__(256) k_f2(const float* __restrict__ pc,
                                            const float* __restrict__ xyz,
                                            const float* __restrict__ scale,
                                            const float* __restrict__ prob,
                                            const float* __restrict__ corners,
                                            int N, int vb) {
    unsigned b = blockIdx.x, t = threadIdx.x;
    if (b >= (unsigned)vb) { bits_job(PB1 + (b - vb), t); return; }

    int i = (int)b * 256 + (int)t;
    if (i >= N) return;
    const float RCP = __fdiv_rn(1.0f, RESF);
    float px = pc[3*i], py = pc[3*i+1], pz = pc[3*i+2];
    float ox = xyz[3*i], oy = xyz[3*i+1], oz = xyz[3*i+2];
    float w  = prob[i];
    float c0x = corners[0], c0y = corners[1], c0z = corners[2];

    float ty = __fadd_rn(py, oy);
    float fy = __fadd_rn(__fmul_rn(__fsub_rn(ty, c0y), RCP), 0.5f);
    int iy = (int)floorf(fy);
    if (iy < 0 || iy >= GY) return;          /* zero weight for all rots */

    float wsx = __fmul_rn(w, scale[3*i]);
    float wsy = __fmul_rn(w, scale[3*i+1]);
    float wsz = __fmul_rn(w, scale[3*i+2]);

    #pragma unroll 4
    for (int r = 0; r < 36; r++) {
        float cth = g_cs[2*r], sth = g_cs[2*r+1];
        float rx = __fadd_rn(__fmul_rn(ox, cth), __fmul_rn(oz, sth));
        float rz = __fadd_rn(-__fmul_rn(ox, sth), __fmul_rn(oz, cth));
        float tx = __fadd_rn(px, rx);
        float tz = __fadd_rn(pz, rz);
        int ix = (int)floorf(__fadd_rn(__fmul_rn(__fsub_rn(tx, c0x), RCP), 0.5f));
        int iz = (int)floorf(__fadd_rn(__fmul_rn(__fsub_rn(tz, c0z), RCP), 0.5f));
        if (ix >= 0 && ix < GX && iz >= 0 && iz < GZ) {
            unsigned cell = ((unsigned)(ix*GY + iy))*GZ + (unsigned)iz;
            asm volatile("red.global.add.v4.f32 [%0], {%1, %2, %3, %4};"
                         :: "l"(&g_grid4[cell]), "f"(w), "f"(wsx), "f"(wsy), "f"(wsz)
                         : "memory");
        }
    }
}

/* ============ K3: colmax + dist + sum(dist)  ||  bits chunk 3 ============ */
__global__ void __launch_bounds__(256) k_f3() {
    __shared__ float sh[256];
    unsigned b = blockIdx.x, t = threadIdx.x;
    if (b >= CMBLKS) { bits_job(PB1 + PB2 + (b - CMBLKS), t); return; }

    unsigned cell = b * 256u + t;                  /* < NC2 exactly */
    unsigned x = cell / GZ, z = cell - x * GZ;
    const float4* col = g_grid4 + (size_t)x * GY * GZ + z;
    float m = col[0].x; int my = 0;
    #pragma unroll 8
    for (int y = 1; y < GY; y++) {
        float v = col[(size_t)y * GZ].x;
        if (v > m) { m = v; my = y; }              /* first index on ties */
    }
    float d = sqrtf(__fadd_rn(m, 1e-7f));          /* XLA pow(x,.5)->sqrt */
    g_dist[cell] = d;
    g_yidx[cell] = my;

    /* block partial sum of dist -> g_D (feeds only the conservative filter) */
    sh[t] = d; __syncthreads();
    for (int o = 128; o > 0; o >>= 1) {
        if (t < (unsigned)o) sh[t] += sh[t + o];
        __syncthreads();
    }
    if (t == 0) atomicAdd(&g_D, sh[0]);
}

/* ============ K4: log(dist) + raw-bits pass threshold (f32) ============
   element can only beat s_T = D/50 if u > T = exp(-50*d_c/D).
   margin 512 mantissa units >> __expf error.                          */
__global__ void __launch_bounds__(256) k_bth() {
    unsigned c = blockIdx.x * 256u + threadIdx.x;
    if (c >= NC2) return;
    float d = g_dist[c];
    g_logd[c] = logf(__fadd_rn(d, 1e-30f));
    float T = __expf(-50.0f * d / g_D);
    int Mi = (int)floorf(T * 8388608.0f) - 512;
    if (Mi < 0) Mi = 0;
    g_bth[c] = ((unsigned)Mi) << 9;
}

/* ============ K5: per-row select + gather + seed dist ============ */
__device__ __forceinline__ void sel_try(unsigned b, unsigned th, int c,
                                        float& bs, int& bi) {
    if (b >= th) {
        unsigned m = b >> 9;
        float u = (m == 0u) ? 1.17549435e-38f
                            : __fadd_rn(__uint_as_float(m | 0x3f800000u), -1.0f);
        float g = -logf(-logf(u));                 /* exact ref gumbel */
        float s = __fadd_rn(g_logd[c], g);
        if (s > bs) { bs = s; bi = c; }
    }
}

__global__ void __launch_bounds__(256) k_sel(const float* __restrict__ corners,
                                             const float* __restrict__ vp, int M) {
    __shared__ float ss[256];
    __shared__ int   si[256];
    __shared__ float sw[3];
    int r = blockIdx.x, tid = threadIdx.x;
    float bs = -3.4e38f; int bi = 0;
    const uint4* thv = reinterpret_cast<const uint4*>(g_bth);

    if (r < (int)RPRE) {
        /* precomputed rows: stream bits from DRAM, vectorized */
        const uint4* rowb = reinterpret_cast<const uint4*>(g_bits + (size_t)r * NC2);
        for (unsigned q = tid; q < NC2/4u; q += 256u) {
            uint4 v  = rowb[q];
            uint4 th = thv[q];
            int c = (int)(q * 4u);
            sel_try(v.x, th.x, c,   bs, bi);
            sel_try(v.y, th.y, c+1, bs, bi);
            sel_try(v.z, th.z, c+2, bs, bi);
            sel_try(v.w, th.w, c+3, bs, bi);
        }
    } else {
        /* inline threefry rows: 4 counters per iteration (ILP) */
        unsigned base = (unsigned)r * NC2;
        for (unsigned q = tid; q < NC2/4u; q += 256u) {
            unsigned j = base + q * 4u;
            unsigned o0, o1, o2, o3;
            tf_bits4(j, j+1u, j+2u, j+3u, o0, o1, o2, o3);
            uint4 th = thv[q];
            int c = (int)(q * 4u);
            sel_try(o0, th.x, c,   bs, bi);
            sel_try(o1, th.y, c+1, bs, bi);
            sel_try(o2, th.z, c+2, bs, bi);
            sel_try(o3, th.w, c+3, bs, bi);
        }
    }

    ss[tid] = bs; si[tid] = bi; __syncthreads();
    for (int o = 128; o > 0; o >>= 1) {
        if (tid < o) {
            float s2 = ss[tid+o]; int i2 = si[tid+o];
            if (s2 > ss[tid] || (s2 == ss[tid] && i2 < si[tid])) { ss[tid] = s2; si[tid] = i2; }
        }
        __syncthreads();
    }

    if (tid == 0) {
        int c  = si[0];
        int xi = c / GZ, zi = c - (c / GZ) * GZ;
        int yi = g_yidx[c];
        float wx = __fadd_rn(__fmul_rn((float)xi, RESF), corners[0]);
        float wy = __fadd_rn(__fmul_rn((float)yi, RESF), corners[1]);
        float wz = __fadd_rn(__fmul_rn((float)zi, RESF), corners[2]);
        g_world[3*r+0] = wx; g_world[3*r+1] = wy; g_world[3*r+2] = wz;
        sw[0] = wx; sw[1] = wy; sw[2] = wz;
        unsigned cell = ((unsigned)(xi*GY + yi))*GZ + (unsigned)zi;
        float4 gv = g_grid4[cell];
        float den = __fadd_rn(gv.x, 1e-7f);
        g_scout[3*r+0] = __fdiv_rn(gv.y, den);
        g_scout[3*r+1] = __fdiv_rn(gv.z, den);
        g_scout[3*r+2] = __fdiv_rn(gv.w, den);
    }
    __syncthreads();

    /* min distance to seed points for this row */
    float wx = sw[0], wy = sw[1], wz = sw[2];
    float mind = 3.4e38f;
    for (int m = tid; m < M; m += 256) {
        float dx = __fsub_rn(wx, vp[3*m]);
        float dy = __fsub_rn(wy, vp[3*m+1]);
        float dz = __fsub_rn(wz, vp[3*m+2]);
        float s  = __fadd_rn(__fadd_rn(__fmul_rn(dx,dx), __fmul_rn(dy,dy)), __fmul_rn(dz,dz));
        mind = fminf(mind, sqrtf(s));
    }
    ss[tid] = mind; __syncthreads();
    for (int o = 128; o > 0; o >>= 1) {
        if (tid < o) ss[tid] = fminf(ss[tid], ss[tid+o]);
        __syncthreads();
    }
    if (tid == 0) g_keep[r] = (ss[0] < 0.3f) ? 1 : 0;
}

/* ============ K6: stable selection + output write ============ */
__global__ void k_finish(float* __restrict__ out) {
    __shared__ int sel[NPROP];
    if (threadIdx.x == 0) {
        int any = 0;
        for (int k = 0; k < NROWS; k++) any |= g_keep[k];
        int cnt = 0;
        if (any) {
            for (int k = 0; k < NROWS && cnt < NPROP; k++) if (g_keep[k])  sel[cnt++] = k;
            for (int k = 0; k < NROWS && cnt < NPROP; k++) if (!g_keep[k]) sel[cnt++] = k;
        } else {
            for (int k = 0; k < NPROP; k++) sel[cnt++] = k;
        }
    }
    __syncthreads();
    int j = threadIdx.x;
    if (j < NPROP) {
        int k = sel[j];
        out[3*j+0] = g_world[3*k+0];
        out[3*j+1] = g_world[3*k+1];
        out[3*j+2] = g_world[3*k+2];
        out[3*NPROP + j] = 0.0f;
        out[4*NPROP + 3*j+0] = g_scout[3*k+0];
        out[4*NPROP + 3*j+1] = g_scout[3*k+1];
        out[4*NPROP + 3*j+2] = g_scout[3*k+2];
    }
}

extern "C" void kernel_launch(void* const* d_in, const int* in_sizes, int n_in,
                              void* d_out, int out_size) {
    const float* pc      = (const float*)d_in[0];
    const float* xyz     = (const float*)d_in[1];
    const float* scale   = (const float*)d_in[2];
    const float* prob    = (const float*)d_in[3];
    const float* corners = (const float*)d_in[4];
    const float* vp      = (const float*)d_in[5];
    int N = in_sizes[0] / 3;
    int M = in_sizes[5] / 3;
    float* out = (float*)d_out;
    int vb = (N + 255) / 256;

    k_f1<<<PB1 + ZBLKS, 256>>>();
    k_f2<<<vb + PB2, 256>>>(pc, xyz, scale, prob, corners, N, vb);
    k_f3<<<CMBLKS + PB3, 256>>>();
    k_bth<<<CMBLKS, 256>>>();
    k_sel<<<NROWS, 256>>>(corners, vp, M);
    k_finish<<<1, 256>>>(out);
}

// round 10
// speedup vs baseline: 1.4494x; 1.1487x over previous
#include <cuda_runtime.h>
#include <math.h>
#include <stdint.h>

#define GX 272
#define GY 112
#define GZ 272
#define NCELL 8286208u            /* GX*GY*GZ */
#define NC2   73984u              /* GX*GZ = 289*256 */
#define NROWS 1024
#define NPROP 256
#define RESF  0.03f

#define RPRE  448u                /* rows with precomputed bits */
#define NPREW (RPRE*NC2)          /* 33,144,832 = 8192*4046 */
#define BWORK 8192u               /* counters per bits-block (256 thr * 32) */
#define PB1   1040u               /* bits blocks fused into K1 */
#define PB2   2200u               /* bits blocks fused into K2 */
#define PB3   806u                /* bits blocks fused into K3 (sum = 4046) */
#define ZBLKS 32368u              /* NCELL/256 float4-zero blocks */
#define CMBLKS 289u               /* NC2/256 */

/* ------------- static device scratch (no allocations) ------------- */
__device__ float4   g_grid4[NCELL];      /* 132 MB: (obj, sx, sy, sz) per cell */
__device__ unsigned g_bits[NPREW];       /* 133 MB: precomputed RNG rows 0..447 */
__device__ float    g_cs[72];
__device__ float    g_dist[NC2];
__device__ float    g_logd[NC2];
__device__ int      g_yidx[NC2];
__device__ unsigned g_bth[NC2];
__device__ float    g_D;
__device__ float    g_world[NROWS*3];
__device__ float    g_scout[NROWS*3];
__device__ int      g_keep[NROWS];

/* ------------- Threefry-2x32, key=(0,42) -------------
   parity = 0x1BD11BDA  =>  ks2 = 0x1BD11BDA ^ 42 = 0x1BD11BF0
   partitionable mode: ctr = (hi=0, lo=j); 32-bit out = bits1 ^ bits2
   *** verified bit-exact in round 6 — do not touch ***              */
#define TFR4(r) { a0 += a1; b0 += b1; c0 += c1; d0 += d1;              \
                  a1 = __funnelshift_l(a1, a1, r); b1 = __funnelshift_l(b1, b1, r); \
                  c1 = __funnelshift_l(c1, c1, r); d1 = __funnelshift_l(d1, d1, r); \
                  a1 ^= a0; b1 ^= b0; c1 ^= c0; d1 ^= d0; }
#define INJ4(k0v, k1v) { a0 += k0v; b0 += k0v; c0 += k0v; d0 += k0v;   \
                         a1 += k1v; b1 += k1v; c1 += k1v; d1 += k1v; }

__device__ __forceinline__ void tf_bits4(unsigned j0, unsigned j1, unsigned j2, unsigned j3,
                                         unsigned& o0, unsigned& o1, unsigned& o2, unsigned& o3) {
    unsigned a0 = 0u, a1 = j0 + 42u;
    unsigned b0 = 0u, b1 = j1 + 42u;
    unsigned c0 = 0u, c1 = j2 + 42u;
    unsigned d0 = 0u, d1 = j3 + 42u;
    TFR4(13) TFR4(15) TFR4(26) TFR4(6)
    INJ4(42u, 0x1BD11BF1u)
    TFR4(17) TFR4(29) TFR4(16) TFR4(24)
    INJ4(0x1BD11BF0u, 2u)
    TFR4(13) TFR4(15) TFR4(26) TFR4(6)
    INJ4(0u, 45u)
    TFR4(17) TFR4(29) TFR4(16) TFR4(24)
    INJ4(42u, 0x1BD11BF4u)
    TFR4(13) TFR4(15) TFR4(26) TFR4(6)
    INJ4(0x1BD11BF0u, 5u)
    o0 = a0 ^ a1; o1 = b0 ^ b1; o2 = c0 ^ c1; o3 = d0 ^ d1;
}

/* bits block: 256 threads produce 8192 consecutive counters, coalesced */
__device__ __forceinline__ void bits_job(unsigned blk, unsigned t) {
    unsigned base = blk * BWORK;
    #pragma unroll
    for (unsigned k = 0; k < 32; k += 4) {
        unsigned i0 = base + (k << 8) + t;
        unsigned o0, o1, o2, o3;
        tf_bits4(i0, i0 + 256u, i0 + 512u, i0 + 768u, o0, o1, o2, o3);
        g_bits[i0]        = o0;
        g_bits[i0 + 256u] = o1;
        g_bits[i0 + 512u] = o2;
        g_bits[i0 + 768u] = o3;
    }
}

/* ============ K1: bits chunk 1  ||  zero grid  ||  cos/sin table ============ */
__global__ void __launch_bounds__(256) k_f1() {
    unsigned b = blockIdx.x, t = threadIdx.x;
    if (b < PB1) {
        if (b == 0) {
            if (t < 36) {
                float tp  = 6.28318530717958647692f;     /* rounds to f32(2pi) */
                float r36 = __fdiv_rn(1.0f, 36.0f);
                float th  = __fmul_rn(__fmul_rn(tp, (float)t), r36);
                g_cs[2*t]   = cosf(th);
                g_cs[2*t+1] = sinf(th);
            }
            if (t == 0) g_D = 0.0f;
        }
        bits_job(b, t);
    } else {
        unsigned zb = b - PB1;
        g_grid4[zb*256u + t] = make_float4(0.f, 0.f, 0.f, 0.f);
    }
}

/* ============ K2: Hough vote scatter (v4 red)  ||  bits chunk 2 ============ */
__global__ void __launch_bounds__(256) k_f2(const float* __restrict__ pc,
                                            const float* __restrict__ xyz,
                                            const float* __restrict__ scale,
                                            const float* __restrict__ prob,
                                            const float* __restrict__ corners,
                                            int N, int vb) {
    unsigned b = blockIdx.x, t = threadIdx.x;
    if (b >= (unsigned)vb) { bits_job(PB1 + (b - vb), t); return; }

    int i = (int)b * 256 + (int)t;
    if (i >= N) return;
    const float RCP = __fdiv_rn(1.0f, RESF);
    float px = pc[3*i], py = pc[3*i+1], pz = pc[3*i+2];
    float ox = xyz[3*i], oy = xyz[3*i+1], oz = xyz[3*i+2];
    float w  = prob[i];
    float c0x = corners[0], c0y = corners[1], c0z = corners[2];

    float ty = __fadd_rn(py, oy);
    float fy = __fadd_rn(__fmul_rn(__fsub_rn(ty, c0y), RCP), 0.5f);
    int iy = (int)floorf(fy);
    if (iy < 0 || iy >= GY) return;          /* zero weight for all rots */

    float wsx = __fmul_rn(w, scale[3*i]);
    float wsy = __fmul_rn(w, scale[3*i+1]);
    float wsz = __fmul_rn(w, scale[3*i+2]);

    #pragma unroll 4
    for (int r = 0; r < 36; r++) {
        float cth = g_cs[2*r], sth = g_cs[2*r+1];
        float rx = __fadd_rn(__fmul_rn(ox, cth), __fmul_rn(oz, sth));
        float rz = __fadd_rn(-__fmul_rn(ox, sth), __fmul_rn(oz, cth));
        float tx = __fadd_rn(px, rx);
        float tz = __fadd_rn(pz, rz);
        int ix = (int)floorf(__fadd_rn(__fmul_rn(__fsub_rn(tx, c0x), RCP), 0.5f));
        int iz = (int)floorf(__fadd_rn(__fmul_rn(__fsub_rn(tz, c0z), RCP), 0.5f));
        if (ix >= 0 && ix < GX && iz >= 0 && iz < GZ) {
            unsigned cell = ((unsigned)(ix*GY + iy))*GZ + (unsigned)iz;
            asm volatile("red.global.add.v4.f32 [%0], {%1, %2, %3, %4};"
                         :: "l"(&g_grid4[cell]), "f"(w), "f"(wsx), "f"(wsy), "f"(wsz)
                         : "memory");
        }
    }
}

/* ============ K3: colmax + dist + sum(dist)  ||  bits chunk 3 ============ */
__global__ void __launch_bounds__(256) k_f3() {
    __shared__ float sh[256];
    unsigned b = blockIdx.x, t = threadIdx.x;
    if (b >= CMBLKS) { bits_job(PB1 + PB2 + (b - CMBLKS), t); return; }

    unsigned cell = b * 256u + t;                  /* < NC2 exactly */
    unsigned x = cell / GZ, z = cell - x * GZ;
    const float4* col = g_grid4 + (size_t)x * GY * GZ + z;
    float m = col[0].x; int my = 0;
    #pragma unroll 8
    for (int y = 1; y < GY; y++) {
        float v = col[(size_t)y * GZ].x;
        if (v > m) { m = v; my = y; }              /* first index on ties */
    }
    float d = sqrtf(__fadd_rn(m, 1e-7f));          /* XLA pow(x,.5)->sqrt */
    g_dist[cell] = d;
    g_yidx[cell] = my;

    /* block partial sum of dist -> g_D (feeds only the conservative filter) */
    sh[t] = d; __syncthreads();
    for (int o = 128; o > 0; o >>= 1) {
        if (t < (unsigned)o) sh[t] += sh[t + o];
        __syncthreads();
    }
    if (t == 0) atomicAdd(&g_D, sh[0]);
}

/* ============ K4: log(dist) + raw-bits pass threshold (f32) ============
   element can only beat s_T = D/50 if u > T = exp(-50*d_c/D).
   margin 512 mantissa units >> __expf error.                          */
__global__ void __launch_bounds__(256) k_bth() {
    unsigned c = blockIdx.x * 256u + threadIdx.x;
    if (c >= NC2) return;
    float d = g_dist[c];
    g_logd[c] = logf(__fadd_rn(d, 1e-30f));
    float T = __expf(-50.0f * d / g_D);
    int Mi = (int)floorf(T * 8388608.0f) - 512;
    if (Mi < 0) Mi = 0;
    g_bth[c] = ((unsigned)Mi) << 9;
}

/* ============ K5: per-row select + gather + seed dist ============ */
__device__ __forceinline__ void sel_try(unsigned b, unsigned th, int c,
                                        float& bs, int& bi) {
    if (b >= th) {
        unsigned m = b >> 9;
        float u = (m == 0u) ? 1.17549435e-38f
                            : __fadd_rn(__uint_as_float(m | 0x3f800000u), -1.0f);
        float g = -logf(-logf(u));                 /* exact ref gumbel */
        float s = __fadd_rn(g_logd[c], g);
        if (s > bs) { bs = s; bi = c; }
    }
}

__global__ void __launch_bounds__(256, 7) k_sel(const float* __restrict__ corners,
                                                const float* __restrict__ vp, int M) {
    __shared__ float ss[256];
    __shared__ int   si[256];
    __shared__ float sw[3];
    int r = blockIdx.x, tid = threadIdx.x;
    float bs = -3.4e38f; int bi = 0;
    const uint4* thv = reinterpret_cast<const uint4*>(g_bth);

    if (r < (int)RPRE) {
        /* precomputed rows: stream bits from DRAM, vectorized */
        const uint4* rowb = reinterpret_cast<const uint4*>(g_bits + (size_t)r * NC2);
        for (unsigned q = tid; q < NC2/4u; q += 256u) {
            uint4 v  = rowb[q];
            uint4 th = thv[q];
            int c = (int)(q * 4u);
            sel_try(v.x, th.x, c,   bs, bi);
            sel_try(v.y, th.y, c+1, bs, bi);
            sel_try(v.z, th.z, c+2, bs, bi);
            sel_try(v.w, th.w, c+3, bs, bi);
        }
    } else {
        /* inline threefry rows: 4 counters per iteration (ILP) */
        unsigned base = (unsigned)r * NC2;
        for (unsigned q = tid; q < NC2/4u; q += 256u) {
            unsigned j = base + q * 4u;
            unsigned o0, o1, o2, o3;
            tf_bits4(j, j+1u, j+2u, j+3u, o0, o1, o2, o3);
            uint4 th = thv[q];
            int c = (int)(q * 4u);
            sel_try(o0, th.x, c,   bs, bi);
            sel_try(o1, th.y, c+1, bs, bi);
            sel_try(o2, th.z, c+2, bs, bi);
            sel_try(o3, th.w, c+3, bs, bi);
        }
    }

    ss[tid] = bs; si[tid] = bi; __syncthreads();
    for (int o = 128; o > 0; o >>= 1) {
        if (tid < o) {
            float s2 = ss[tid+o]; int i2 = si[tid+o];
            if (s2 > ss[tid] || (s2 == ss[tid] && i2 < si[tid])) { ss[tid] = s2; si[tid] = i2; }
        }
        __syncthreads();
    }

    if (tid == 0) {
        int c  = si[0];
        int xi = c / GZ, zi = c - (c / GZ) * GZ;
        int yi = g_yidx[c];
        float wx = __fadd_rn(__fmul_rn((float)xi, RESF), corners[0]);
        float wy = __fadd_rn(__fmul_rn((float)yi, RESF), corners[1]);
        float wz = __fadd_rn(__fmul_rn((float)zi, RESF), corners[2]);
        g_world[3*r+0] = wx; g_world[3*r+1] = wy; g_world[3*r+2] = wz;
        sw[0] = wx; sw[1] = wy; sw[2] = wz;
        unsigned cell = ((unsigned)(xi*GY + yi))*GZ + (unsigned)zi;
        float4 gv = g_grid4[cell];
        float den = __fadd_rn(gv.x, 1e-7f);
        g_scout[3*r+0] = __fdiv_rn(gv.y, den);
        g_scout[3*r+1] = __fdiv_rn(gv.z, den);
        g_scout[3*r+2] = __fdiv_rn(gv.w, den);
    }
    __syncthreads();

    /* min distance to seed points for this row */
    float wx = sw[0], wy = sw[1], wz = sw[2];
    float mind = 3.4e38f;
    for (int m = tid; m < M; m += 256) {
        float dx = __fsub_rn(wx, vp[3*m]);
        float dy = __fsub_rn(wy, vp[3*m+1]);
        float dz = __fsub_rn(wz, vp[3*m+2]);
        float s  = __fadd_rn(__fadd_rn(__fmul_rn(dx,dx), __fmul_rn(dy,dy)), __fmul_rn(dz,dz));
        mind = fminf(mind, sqrtf(s));
    }
    ss[tid] = mind; __syncthreads();
    for (int o = 128; o > 0; o >>= 1) {
        if (tid < o) ss[tid] = fminf(ss[tid], ss[tid+o]);
        __syncthreads();
    }
    if (tid == 0) g_keep[r] = (ss[0] < 0.3f) ? 1 : 0;
}

/* ============ K6: parallel stable selection + output write ============ */
__global__ void __launch_bounds__(1024) k_finish(float* __restrict__ out) {
    __shared__ int sk[NROWS];
    int t = threadIdx.x;                       /* 1024 threads, one per row */
    int kp = g_keep[t];
    sk[t] = kp; __syncthreads();

    /* inclusive prefix sum of keep flags (Hillis-Steele) */
    for (int o = 1; o < NROWS; o <<= 1) {
        int val = sk[t];
        if (t >= o) val += sk[t - o];
        __syncthreads();
        sk[t] = val;
        __syncthreads();
    }
    int incl  = sk[t];
    int total = sk[NROWS - 1];

    /* output slot for this row under stable argsort(where(keep,0,1)) */
    int slot;
    if (total > 0) slot = kp ? (incl - 1) : (total + (t - incl));
    else           slot = t;                   /* keep.any()==False -> identity */

    if (slot < NPROP) {
        out[3*slot+0] = g_world[3*t+0];
        out[3*slot+1] = g_world[3*t+1];
        out[3*slot+2] = g_world[3*t+2];
        out[4*NPROP + 3*slot+0] = g_scout[3*t+0];
        out[4*NPROP + 3*slot+1] = g_scout[3*t+1];
        out[4*NPROP + 3*slot+2] = g_scout[3*t+2];
    }
    if (t < NPROP) out[3*NPROP + t] = 0.0f;    /* probs = zeros */
}

extern "C" void kernel_launch(void* const* d_in, const int* in_sizes, int n_in,
                              void* d_out, int out_size) {
    const float* pc      = (const float*)d_in[0];
    const float* xyz     = (const float*)d_in[1];
    const float* scale   = (const float*)d_in[2];
    const float* prob    = (const float*)d_in[3];
    const float* corners = (const float*)d_in[4];
    const float* vp      = (const float*)d_in[5];
    int N = in_sizes[0] / 3;
    int M = in_sizes[5] / 3;
    float* out = (float*)d_out;
    int vb = (N + 255) / 256;

    k_f1<<<PB1 + ZBLKS, 256>>>();
    k_f2<<<vb + PB2, 256>>>(pc, xyz, scale, prob, corners, N, vb);
    k_f3<<<CMBLKS + PB3, 256>>>();
    k_bth<<<CMBLKS, 256>>>();
    k_sel<<<NROWS, 256>>>(corners, vp, M);
    k_finish<<<1, 1024>>>(out);
}

// round 11
// speedup vs baseline: 1.6154x; 1.1146x over previous
#include <cuda_runtime.h>
#include <math.h>
#include <stdint.h>

#define GX 272
#define GY 112
#define GZ 272
#define NCELL 8286208u            /* GX*GY*GZ */
#define NC2   73984u              /* GX*GZ = 289*256 */
#define NROWS 1024
#define NPROP 256
#define RESF  0.03f

#define RPRE  448u                /* rows with precomputed bits */
#define NPREW (RPRE*NC2)          /* 33,144,832 = 8192*4046 */
#define BWORK 8192u               /* counters per bits-block (256 thr * 32) */
#define PB1   1040u               /* bits blocks fused into K1 */
#define PB2   2200u               /* bits blocks fused into K2 */
#define PB3   806u                /* bits blocks fused into K3 (sum = 4046) */
#define ZBLKS 32368u              /* NCELL/256 float4-zero blocks */
#define CMBLKS 289u               /* NC2/256 */

/* ------------- static device scratch (no allocations) ------------- */
__device__ float4   g_grid4[NCELL];      /* 132 MB: (obj, sx, sy, sz) per cell */
__device__ unsigned g_bits[NPREW];       /* 133 MB: precomputed RNG rows 0..447 */
__device__ float    g_cs[72];
__device__ float    g_dist[NC2];
__device__ float    g_logd[NC2];
__device__ int      g_yidx[NC2];
__device__ unsigned g_bth[NC2];
__device__ float    g_D;
__device__ float    g_world[NROWS*3];
__device__ float    g_scout[NROWS*3];
__device__ int      g_keep[NROWS];

/* ---- pipe-balancing add: IMAD on fma pipe; `one`==1 is a kernel param
   so ptxas cannot strength-reduce it back to IADD3 (alu pipe). Exact. ---- */
__device__ __forceinline__ unsigned addv(unsigned a, unsigned b, unsigned one) {
    unsigned r;
    asm("mad.lo.u32 %0, %1, %2, %3;" : "=r"(r) : "r"(a), "r"(one), "r"(b));
    return r;
}
template<unsigned K>
__device__ __forceinline__ unsigned addk(unsigned a, unsigned one) {
    if constexpr (K == 0u) { return a; }
    else {
        unsigned r;
        asm("mad.lo.u32 %0, %1, %2, %3;" : "=r"(r) : "n"(K), "r"(one), "r"(a));
        return r;
    }
}

/* ------------- Threefry-2x32, key=(0,42) -------------
   parity = 0x1BD11BDA  =>  ks2 = 0x1BD11BDA ^ 42 = 0x1BD11BF0
   partitionable mode: ctr = (hi=0, lo=j); 32-bit out = bits1 ^ bits2
   *** verified bit-exact in round 6 — do not touch the math ***      */
#define TFR4(r) { a0 = addv(a0, a1, one); b0 = addv(b0, b1, one);       \
                  c0 = addv(c0, c1, one); d0 = addv(d0, d1, one);       \
                  a1 = __funnelshift_l(a1, a1, r); b1 = __funnelshift_l(b1, b1, r); \
                  c1 = __funnelshift_l(c1, c1, r); d1 = __funnelshift_l(d1, d1, r); \
                  a1 ^= a0; b1 ^= b0; c1 ^= c0; d1 ^= d0; }
#define INJ4K(K0, K1) { a0 = addk<K0>(a0, one); b0 = addk<K0>(b0, one); \
                        c0 = addk<K0>(c0, one); d0 = addk<K0>(d0, one); \
                        a1 = addk<K1>(a1, one); b1 = addk<K1>(b1, one); \
                        c1 = addk<K1>(c1, one); d1 = addk<K1>(d1, one); }

__device__ __forceinline__ void tf_bits4(unsigned j0, unsigned j1, unsigned j2, unsigned j3,
                                         unsigned& o0, unsigned& o1, unsigned& o2, unsigned& o3,
                                         unsigned one) {
    unsigned a0 = 0u, a1 = addk<42u>(j0, one);
    unsigned b0 = 0u, b1 = addk<42u>(j1, one);
    unsigned c0 = 0u, c1 = addk<42u>(j2, one);
    unsigned d0 = 0u, d1 = addk<42u>(j3, one);
    TFR4(13) TFR4(15) TFR4(26) TFR4(6)
    INJ4K(42u, 0x1BD11BF1u)
    TFR4(17) TFR4(29) TFR4(16) TFR4(24)
    INJ4K(0x1BD11BF0u, 2u)
    TFR4(13) TFR4(15) TFR4(26) TFR4(6)
    INJ4K(0u, 45u)
    TFR4(17) TFR4(29) TFR4(16) TFR4(24)
    INJ4K(42u, 0x1BD11BF4u)
    TFR4(13) TFR4(15) TFR4(26) TFR4(6)
    INJ4K(0x1BD11BF0u, 5u)
    o0 = a0 ^ a1; o1 = b0 ^ b1; o2 = c0 ^ c1; o3 = d0 ^ d1;
}

/* bits block: 256 threads produce 8192 consecutive counters, coalesced */
__device__ __forceinline__ void bits_job(unsigned blk, unsigned t, unsigned one) {
    unsigned base = blk * BWORK;
    #pragma unroll
    for (unsigned k = 0; k < 32; k += 4) {
        unsigned i0 = base + (k << 8) + t;
        unsigned o0, o1, o2, o3;
        tf_bits4(i0, i0 + 256u, i0 + 512u, i0 + 768u, o0, o1, o2, o3, one);
        g_bits[i0]        = o0;
        g_bits[i0 + 256u] = o1;
        g_bits[i0 + 512u] = o2;
        g_bits[i0 + 768u] = o3;
    }
}

/* ============ K1: bits chunk 1  ||  zero grid  ||  cos/sin table ============ */
__global__ void __launch_bounds__(256) k_f1(unsigned one) {
    unsigned b = blockIdx.x, t = threadIdx.x;
    if (b < PB1) {
        if (b == 0) {
            if (t < 36) {
                float tp  = 6.28318530717958647692f;     /* rounds to f32(2pi) */
                float r36 = __fdiv_rn(1.0f, 36.0f);
                float th  = __fmul_rn(__fmul_rn(tp, (float)t), r36);
                g_cs[2*t]   = cosf(th);
                g_cs[2*t+1] = sinf(th);
            }
            if (t == 0) g_D = 0.0f;
        }
        bits_job(b, t, one);
    } else {
        unsigned zb = b - PB1;
        g_grid4[zb*256u + t] = make_float4(0.f, 0.f, 0.f, 0.f);
    }
}

/* ============ K2: Hough vote scatter (v4 red)  ||  bits chunk 2 ============ */
__global__ void __launch_bounds__(256) k_f2(const float* __restrict__ pc,
                                            const float* __restrict__ xyz,
                                            const float* __restrict__ scale,
                                            const float* __restrict__ prob,
                                            const float* __restrict__ corners,
                                            int N, int vb, unsigned one) {
    unsigned b = blockIdx.x, t = threadIdx.x;
    if (b >= (unsigned)vb) { bits_job(PB1 + (b - vb), t, one); return; }

    int i = (int)b * 256 + (int)t;
    if (i >= N) return;
    const float RCP = __fdiv_rn(1.0f, RESF);
    float px = pc[3*i], py = pc[3*i+1], pz = pc[3*i+2];
    float ox = xyz[3*i], oy = xyz[3*i+1], oz = xyz[3*i+2];
    float w  = prob[i];
    float c0x = corners[0], c0y = corners[1], c0z = corners[2];

    float ty = __fadd_rn(py, oy);
    float fy = __fadd_rn(__fmul_rn(__fsub_rn(ty, c0y), RCP), 0.5f);
    int iy = (int)floorf(fy);
    if (iy < 0 || iy >= GY) return;          /* zero weight for all rots */

    float wsx = __fmul_rn(w, scale[3*i]);
    float wsy = __fmul_rn(w, scale[3*i+1]);
    float wsz = __fmul_rn(w, scale[3*i+2]);

    #pragma unroll 4
    for (int r = 0; r < 36; r++) {
        float cth = g_cs[2*r], sth = g_cs[2*r+1];
        float rx = __fadd_rn(__fmul_rn(ox, cth), __fmul_rn(oz, sth));
        float rz = __fadd_rn(-__fmul_rn(ox, sth), __fmul_rn(oz, cth));
        float tx = __fadd_rn(px, rx);
        float tz = __fadd_rn(pz, rz);
        int ix = (int)floorf(__fadd_rn(__fmul_rn(__fsub_rn(tx, c0x), RCP), 0.5f));
        int iz = (int)floorf(__fadd_rn(__fmul_rn(__fsub_rn(tz, c0z), RCP), 0.5f));
        if (ix >= 0 && ix < GX && iz >= 0 && iz < GZ) {
            unsigned cell = ((unsigned)(ix*GY + iy))*GZ + (unsigned)iz;
            asm volatile("red.global.add.v4.f32 [%0], {%1, %2, %3, %4};"
                         :: "l"(&g_grid4[cell]), "f"(w), "f"(wsx), "f"(wsy), "f"(wsz)
                         : "memory");
        }
    }
}

/* ============ K3: colmax + dist + sum(dist)  ||  bits chunk 3 ============ */
__global__ void __launch_bounds__(256) k_f3(unsigned one) {
    __shared__ float sh[256];
    unsigned b = blockIdx.x, t = threadIdx.x;
    if (b >= CMBLKS) { bits_job(PB1 + PB2 + (b - CMBLKS), t, one); return; }

    unsigned cell = b * 256u + t;                  /* < NC2 exactly */
    unsigned x = cell / GZ, z = cell - x * GZ;
    const float4* col = g_grid4 + (size_t)x * GY * GZ + z;
    float m = col[0].x; int my = 0;
    #pragma unroll 8
    for (int y = 1; y < GY; y++) {
        float v = col[(size_t)y * GZ].x;
        if (v > m) { m = v; my = y; }              /* first index on ties */
    }
    float d = sqrtf(__fadd_rn(m, 1e-7f));          /* XLA pow(x,.5)->sqrt */
    g_dist[cell] = d;
    g_yidx[cell] = my;

    /* block partial sum of dist -> g_D (feeds only the conservative filter) */
    sh[t] = d; __syncthreads();
    for (int o = 128; o > 0; o >>= 1) {
        if (t < (unsigned)o) sh[t] += sh[t + o];
        __syncthreads();
    }
    if (t == 0) atomicAdd(&g_D, sh[0]);
}

/* ============ K4: log(dist) + raw-bits pass threshold (f32) ============
   element can only beat s_T = D/50 if u > T = exp(-50*d_c/D).
   margin 512 mantissa units >> __expf error.                          */
__global__ void __launch_bounds__(256) k_bth() {
    unsigned c = blockIdx.x * 256u + threadIdx.x;
    if (c >= NC2) return;
    float d = g_dist[c];
    g_logd[c] = logf(__fadd_rn(d, 1e-30f));
    float T = __expf(-50.0f * d / g_D);
    int Mi = (int)floorf(T * 8388608.0f) - 512;
    if (Mi < 0) Mi = 0;
    g_bth[c] = ((unsigned)Mi) << 9;
}

/* ============ K5: per-row select + gather + seed dist ============ */
__device__ __forceinline__ void sel_try(unsigned b, unsigned th, int c,
                                        float& bs, int& bi) {
    if (b >= th) {
        unsigned m = b >> 9;
        float u = (m == 0u) ? 1.17549435e-38f
                            : __fadd_rn(__uint_as_float(m | 0x3f800000u), -1.0f);
        float g = -logf(-logf(u));                 /* exact ref gumbel */
        float s = __fadd_rn(g_logd[c], g);
        if (s > bs) { bs = s; bi = c; }
    }
}

__global__ void __launch_bounds__(256, 7) k_sel(const float* __restrict__ corners,
                                                const float* __restrict__ vp, int M,
                                                unsigned one) {
    __shared__ float ss[256];
    __shared__ int   si[256];
    __shared__ float sw[3];
    int r = blockIdx.x, tid = threadIdx.x;
    float bs = -3.4e38f; int bi = 0;
    const uint4* thv = reinterpret_cast<const uint4*>(g_bth);

    if (r < (int)RPRE) {
        /* precomputed rows: stream bits from DRAM, vectorized */
        const uint4* rowb = reinterpret_cast<const uint4*>(g_bits + (size_t)r * NC2);
        for (unsigned q = tid; q < NC2/4u; q += 256u) {
            uint4 v  = rowb[q];
            uint4 th = thv[q];
            int c = (int)(q * 4u);
            sel_try(v.x, th.x, c,   bs, bi);
            sel_try(v.y, th.y, c+1, bs, bi);
            sel_try(v.z, th.z, c+2, bs, bi);
            sel_try(v.w, th.w, c+3, bs, bi);
        }
    } else {
        /* inline threefry rows: 4 counters per iteration (ILP) */
        unsigned base = (unsigned)r * NC2;
        for (unsigned q = tid; q < NC2/4u; q += 256u) {
            unsigned j = base + q * 4u;
            unsigned o0, o1, o2, o3;
            tf_bits4(j, j+1u, j+2u, j+3u, o0, o1, o2, o3, one);
            uint4 th = thv[q];
            int c = (int)(q * 4u);
            sel_try(o0, th.x, c,   bs, bi);
            sel_try(o1, th.y, c+1, bs, bi);
            sel_try(o2, th.z, c+2, bs, bi);
            sel_try(o3, th.w, c+3, bs, bi);
        }
    }

    ss[tid] = bs; si[tid] = bi; __syncthreads();
    for (int o = 128; o > 0; o >>= 1) {
        if (tid < o) {
            float s2 = ss[tid+o]; int i2 = si[tid+o];
            if (s2 > ss[tid] || (s2 == ss[tid] && i2 < si[tid])) { ss[tid] = s2; si[tid] = i2; }
        }
        __syncthreads();
    }

    if (tid == 0) {
        int c  = si[0];
        int xi = c / GZ, zi = c - (c / GZ) * GZ;
        int yi = g_yidx[c];
        float wx = __fadd_rn(__fmul_rn((float)xi, RESF), corners[0]);
        float wy = __fadd_rn(__fmul_rn((float)yi, RESF), corners[1]);
        float wz = __fadd_rn(__fmul_rn((float)zi, RESF), corners[2]);
        g_world[3*r+0] = wx; g_world[3*r+1] = wy; g_world[3*r+2] = wz;
        sw[0] = wx; sw[1] = wy; sw[2] = wz;
        unsigned cell = ((unsigned)(xi*GY + yi))*GZ + (unsigned)zi;
        float4 gv = g_grid4[cell];
        float den = __fadd_rn(gv.x, 1e-7f);
        g_scout[3*r+0] = __fdiv_rn(gv.y, den);
        g_scout[3*r+1] = __fdiv_rn(gv.z, den);
        g_scout[3*r+2] = __fdiv_rn(gv.w, den);
    }
    __syncthreads();

    /* min distance to seed points for this row */
    float wx = sw[0], wy = sw[1], wz = sw[2];
    float mind = 3.4e38f;
    for (int m = tid; m < M; m += 256) {
        float dx = __fsub_rn(wx, vp[3*m]);
        float dy = __fsub_rn(wy, vp[3*m+1]);
        float dz = __fsub_rn(wz, vp[3*m+2]);
        float s  = __fadd_rn(__fadd_rn(__fmul_rn(dx,dx), __fmul_rn(dy,dy)), __fmul_rn(dz,dz));
        mind = fminf(mind, sqrtf(s));
    }
    ss[tid] = mind; __syncthreads();
    for (int o = 128; o > 0; o >>= 1) {
        if (tid < o) ss[tid] = fminf(ss[tid], ss[tid+o]);
        __syncthreads();
    }
    if (tid == 0) g_keep[r] = (ss[0] < 0.3f) ? 1 : 0;
}

/* ============ K6: parallel stable selection + output write ============ */
__global__ void __launch_bounds__(1024) k_finish(float* __restrict__ out) {
    __shared__ int sk[NROWS];
    int t = threadIdx.x;                       /* 1024 threads, one per row */
    int kp = g_keep[t];
    sk[t] = kp; __syncthreads();

    /* inclusive prefix sum of keep flags (Hillis-Steele) */
    for (int o = 1; o < NROWS; o <<= 1) {
        int val = sk[t];
        if (t >= o) val += sk[t - o];
        __syncthreads();
        sk[t] = val;
        __syncthreads();
    }
    int incl  = sk[t];
    int total = sk[NROWS - 1];

    /* output slot for this row under stable argsort(where(keep,0,1)) */
    int slot;
    if (total > 0) slot = kp ? (incl - 1) : (total + (t - incl));
    else           slot = t;                   /* keep.any()==False -> identity */

    if (slot < NPROP) {
        out[3*slot+0] = g_world[3*t+0];
        out[3*slot+1] = g_world[3*t+1];
        out[3*slot+2] = g_world[3*t+2];
        out[4*NPROP + 3*slot+0] = g_scout[3*t+0];
        out[4*NPROP + 3*slot+1] = g_scout[3*t+1];
        out[4*NPROP + 3*slot+2] = g_scout[3*t+2];
    }
    if (t < NPROP) out[3*NPROP + t] = 0.0f;    /* probs = zeros */
}

extern "C" void kernel_launch(void* const* d_in, const int* in_sizes, int n_in,
                              void* d_out, int out_size) {
    const float* pc      = (const float*)d_in[0];
    const float* xyz     = (const float*)d_in[1];
    const float* scale   = (const float*)d_in[2];
    const float* prob    = (const float*)d_in[3];
    const float* corners = (const float*)d_in[4];
    const float* vp      = (const float*)d_in[5];
    int N = in_sizes[0] / 3;
    int M = in_sizes[5] / 3;
    float* out = (float*)d_out;
    int vb = (N + 255) / 256;
    unsigned one = 1u;                          /* opaque to ptxas: keeps IMAD on fma pipe */

    k_f1<<<PB1 + ZBLKS, 256>>>(one);
    k_f2<<<vb + PB2, 256>>>(pc, xyz, scale, prob, corners, N, vb, one);
    k_f3<<<CMBLKS + PB3, 256>>>(one);
    k_bth<<<CMBLKS, 256>>>();
    k_sel<<<NROWS, 256>>>(corners, vp, M, one);
    k_finish<<<1, 1024>>>(out);
}

// round 12
// speedup vs baseline: 1.7053x; 1.0556x over previous
#include <cuda_runtime.h>
#include <math.h>
#include <stdint.h>

#define GX 272
#define GY 112
#define GZ 272
#define NCELL 8286208u            /* GX*GY*GZ */
#define NC2   73984u              /* GX*GZ = 289*256 */
#define NROWS 1024
#define NPROP 256
#define RESF  0.03f

#define RPRE  512u                /* rows with precomputed bits */
#define NPREW (RPRE*NC2)          /* 37,879,808 = 8192*4624 */
#define BWORK 8192u               /* counters per bits-block (256 thr * 32) */
#define PB1   1200u               /* bits blocks fused into K1 */
#define PB2   2400u               /* bits blocks fused into K2 */
#define PB3   1024u               /* bits blocks fused into K3 (sum = 4624) */
#define ZBLKS 32368u              /* NCELL/256 float4-zero blocks */
#define CMBLKS 289u               /* NC2/256 */

/* ------------- static device scratch (no allocations) ------------- */
__device__ float4   g_grid4[NCELL];      /* 132 MB: (obj, sx, sy, sz) per cell */
__device__ unsigned g_bits[NPREW];       /* 152 MB: precomputed RNG rows 0..511 */
__device__ float    g_cs[72];
__device__ float    g_dist[NC2];
__device__ float    g_logd[NC2];
__device__ int      g_yidx[NC2];
__device__ unsigned g_bth[NC2];
__device__ float    g_D;
__device__ float    g_world[NROWS*3];
__device__ float    g_scout[NROWS*3];
__device__ int      g_keep[NROWS];

/* ---- pipe-balancing add: IMAD on fma pipe; `one`==1 is a kernel param
   so ptxas cannot strength-reduce it back to IADD3 (alu pipe). Exact. ---- */
__device__ __forceinline__ unsigned addv(unsigned a, unsigned b, unsigned one) {
    unsigned r;
    asm("mad.lo.u32 %0, %1, %2, %3;" : "=r"(r) : "r"(a), "r"(one), "r"(b));
    return r;
}
template<unsigned K>
__device__ __forceinline__ unsigned addk(unsigned a, unsigned one) {
    if constexpr (K == 0u) { return a; }
    else {
        unsigned r;
        asm("mad.lo.u32 %0, %1, %2, %3;" : "=r"(r) : "n"(K), "r"(one), "r"(a));
        return r;
    }
}
/* wide-mul rotate on the fma pipe: rotl(x,r) = lo(x*2^r) | hi(x*2^r);
   the OR fuses with the round xor into one LOP3: (lo|hi)^x0.          */
__device__ __forceinline__ unsigned wrotx(unsigned x, unsigned m, unsigned x0) {
    unsigned long long y = (unsigned long long)x * m;
    return (((unsigned)y) | ((unsigned)(y >> 32))) ^ x0;
}

/* ------------- Threefry-2x32, key=(0,42) -------------
   parity = 0x1BD11BDA  =>  ks2 = 0x1BD11BDA ^ 42 = 0x1BD11BF0
   partitionable mode: ctr = (hi=0, lo=j); 32-bit out = bits1 ^ bits2
   *** verified bit-exact in round 6 — integer identities only ***     */
/* SHF-form round (alu pipe) */
#define TFR4_S(r) { a0 = addv(a0, a1, one); b0 = addv(b0, b1, one);     \
                    c0 = addv(c0, c1, one); d0 = addv(d0, d1, one);     \
                    a1 = __funnelshift_l(a1, a1, r) ^ a0;               \
                    b1 = __funnelshift_l(b1, b1, r) ^ b0;               \
                    c1 = __funnelshift_l(c1, c1, r) ^ c0;               \
                    d1 = __funnelshift_l(d1, d1, r) ^ d0; }
/* wide-mul-form round (rot on fma pipe) */
#define TFR4_W(m) { a0 = addv(a0, a1, one); b0 = addv(b0, b1, one);     \
                    c0 = addv(c0, c1, one); d0 = addv(d0, d1, one);     \
                    a1 = wrotx(a1, m, a0); b1 = wrotx(b1, m, b0);       \
                    c1 = wrotx(c1, m, c0); d1 = wrotx(d1, m, d0); }
/* first round: x0==0 so the add is a copy; rot13 -> wide form */
#define TFR4_FIRST(m) { a0 = a1; b0 = b1; c0 = c1; d0 = d1;             \
                    a1 = wrotx(a1, m, a0); b1 = wrotx(b1, m, b0);       \
                    c1 = wrotx(c1, m, c0); d1 = wrotx(d1, m, d0); }
#define INJ4K(K0, K1) { a0 = addk<K0>(a0, one); b0 = addk<K0>(b0, one); \
                        c0 = addk<K0>(c0, one); d0 = addk<K0>(d0, one); \
                        a1 = addk<K1>(a1, one); b1 = addk<K1>(b1, one); \
                        c1 = addk<K1>(c1, one); d1 = addk<K1>(d1, one); }

__device__ __forceinline__ void tf_bits4(unsigned j0, unsigned j1, unsigned j2, unsigned j3,
                                         unsigned& o0, unsigned& o1, unsigned& o2, unsigned& o3,
                                         unsigned one, unsigned m13, unsigned m15) {
    unsigned a0, a1 = addk<42u>(j0, one);
    unsigned b0, b1 = addk<42u>(j1, one);
    unsigned c0, c1 = addk<42u>(j2, one);
    unsigned d0, d1 = addk<42u>(j3, one);
    TFR4_FIRST(m13) TFR4_W(m15) TFR4_S(26) TFR4_S(6)
    INJ4K(42u, 0x1BD11BF1u)
    TFR4_S(17) TFR4_S(29) TFR4_S(16) TFR4_S(24)
    INJ4K(0x1BD11BF0u, 2u)
    TFR4_W(m13) TFR4_W(m15) TFR4_S(26) TFR4_S(6)
    INJ4K(0u, 45u)
    TFR4_S(17) TFR4_S(29) TFR4_S(16) TFR4_S(24)
    INJ4K(42u, 0x1BD11BF4u)
    TFR4_W(m13) TFR4_W(m15) TFR4_S(26) TFR4_S(6)
    INJ4K(0x1BD11BF0u, 5u)
    o0 = a0 ^ a1; o1 = b0 ^ b1; o2 = c0 ^ c1; o3 = d0 ^ d1;
}

/* bits block: 256 threads produce 8192 consecutive counters, coalesced */
__device__ __forceinline__ void bits_job(unsigned blk, unsigned t,
                                         unsigned one, unsigned m13, unsigned m15) {
    unsigned base = blk * BWORK;
    #pragma unroll
    for (unsigned k = 0; k < 32; k += 4) {
        unsigned i0 = base + (k << 8) + t;
        unsigned o0, o1, o2, o3;
        tf_bits4(i0, i0 + 256u, i0 + 512u, i0 + 768u, o0, o1, o2, o3, one, m13, m15);
        g_bits[i0]        = o0;
        g_bits[i0 + 256u] = o1;
        g_bits[i0 + 512u] = o2;
        g_bits[i0 + 768u] = o3;
    }
}

/* ============ K1: bits chunk 1  ||  zero grid  ||  cos/sin table ============ */
__global__ void __launch_bounds__(256) k_f1(unsigned one) {
    unsigned b = blockIdx.x, t = threadIdx.x;
    if (b < PB1) {
        if (b == 0) {
            if (t < 36) {
                float tp  = 6.28318530717958647692f;     /* rounds to f32(2pi) */
                float r36 = __fdiv_rn(1.0f, 36.0f);
                float th  = __fmul_rn(__fmul_rn(tp, (float)t), r36);
                g_cs[2*t]   = cosf(th);
                g_cs[2*t+1] = sinf(th);
            }
            if (t == 0) g_D = 0.0f;
        }
        bits_job(b, t, one, one << 13, one << 15);
    } else {
        unsigned zb = b - PB1;
        g_grid4[zb*256u + t] = make_float4(0.f, 0.f, 0.f, 0.f);
    }
}

/* ============ K2: Hough vote scatter (v4 red)  ||  bits chunk 2 ============ */
__global__ void __launch_bounds__(256) k_f2(const float* __restrict__ pc,
                                            const float* __restrict__ xyz,
                                            const float* __restrict__ scale,
                                            const float* __restrict__ prob,
                                            const float* __restrict__ corners,
                                            int N, int vb, unsigned one) {
    unsigned b = blockIdx.x, t = threadIdx.x;
    if (b >= (unsigned)vb) { bits_job(PB1 + (b - vb), t, one, one << 13, one << 15); return; }

    int i = (int)b * 256 + (int)t;
    if (i >= N) return;
    const float RCP = __fdiv_rn(1.0f, RESF);
    float px = pc[3*i], py = pc[3*i+1], pz = pc[3*i+2];
    float ox = xyz[3*i], oy = xyz[3*i+1], oz = xyz[3*i+2];
    float w  = prob[i];
    float c0x = corners[0], c0y = corners[1], c0z = corners[2];

    float ty = __fadd_rn(py, oy);
    float fy = __fadd_rn(__fmul_rn(__fsub_rn(ty, c0y), RCP), 0.5f);
    int iy = (int)floorf(fy);
    if (iy < 0 || iy >= GY) return;          /* zero weight for all rots */

    float wsx = __fmul_rn(w, scale[3*i]);
    float wsy = __fmul_rn(w, scale[3*i+1]);
    float wsz = __fmul_rn(w, scale[3*i+2]);

    #pragma unroll 4
    for (int r = 0; r < 36; r++) {
        float cth = g_cs[2*r], sth = g_cs[2*r+1];
        float rx = __fadd_rn(__fmul_rn(ox, cth), __fmul_rn(oz, sth));
        float rz = __fadd_rn(-__fmul_rn(ox, sth), __fmul_rn(oz, cth));
        float tx = __fadd_rn(px, rx);
        float tz = __fadd_rn(pz, rz);
        int ix = (int)floorf(__fadd_rn(__fmul_rn(__fsub_rn(tx, c0x), RCP), 0.5f));
        int iz = (int)floorf(__fadd_rn(__fmul_rn(__fsub_rn(tz, c0z), RCP), 0.5f));
        if (ix >= 0 && ix < GX && iz >= 0 && iz < GZ) {
            unsigned cell = ((unsigned)(ix*GY + iy))*GZ + (unsigned)iz;
            asm volatile("red.global.add.v4.f32 [%0], {%1, %2, %3, %4};"
                         :: "l"(&g_grid4[cell]), "f"(w), "f"(wsx), "f"(wsy), "f"(wsz)
                         : "memory");
        }
    }
}

/* ============ K3: colmax + dist + sum(dist)  ||  bits chunk 3 ============ */
__global__ void __launch_bounds__(256) k_f3(unsigned one) {
    __shared__ float sh[256];
    unsigned b = blockIdx.x, t = threadIdx.x;
    if (b >= CMBLKS) { bits_job(PB1 + PB2 + (b - CMBLKS), t, one, one << 13, one << 15); return; }

    unsigned cell = b * 256u + t;                  /* < NC2 exactly */
    unsigned x = cell / GZ, z = cell - x * GZ;
    const float4* col = g_grid4 + (size_t)x * GY * GZ + z;
    float m = col[0].x; int my = 0;
    #pragma unroll 8
    for (int y = 1; y < GY; y++) {
        float v = col[(size_t)y * GZ].x;
        if (v > m) { m = v; my = y; }              /* first index on ties */
    }
    float d = sqrtf(__fadd_rn(m, 1e-7f));          /* XLA pow(x,.5)->sqrt */
    g_dist[cell] = d;
    g_yidx[cell] = my;

    /* block partial sum of dist -> g_D (feeds only the conservative filter) */
    sh[t] = d; __syncthreads();
    for (int o = 128; o > 0; o >>= 1) {
        if (t < (unsigned)o) sh[t] += sh[t + o];
        __syncthreads();
    }
    if (t == 0) atomicAdd(&g_D, sh[0]);
}

/* ============ K4: log(dist) + raw-bits pass threshold (f32) ============
   element can only beat s_T = D/50 if u > T = exp(-50*d_c/D).
   margin 512 mantissa units >> __expf error.                          */
__global__ void __launch_bounds__(256) k_bth() {
    unsigned c = blockIdx.x * 256u + threadIdx.x;
    if (c >= NC2) return;
    float d = g_dist[c];
    g_logd[c] = logf(__fadd_rn(d, 1e-30f));
    float T = __expf(-50.0f * d / g_D);
    int Mi = (int)floorf(T * 8388608.0f) - 512;
    if (Mi < 0) Mi = 0;
    g_bth[c] = ((unsigned)Mi) << 9;
}

/* ============ K5: per-row select + gather + seed dist ============ */
__device__ __forceinline__ void sel_try(unsigned b, unsigned th, int c,
                                        float& bs, int& bi) {
    if (b >= th) {
        unsigned m = b >> 9;
        float u = (m == 0u) ? 1.17549435e-38f
                            : __fadd_rn(__uint_as_float(m | 0x3f800000u), -1.0f);
        float g = -logf(-logf(u));                 /* exact ref gumbel */
        float s = __fadd_rn(g_logd[c], g);
        if (s > bs) { bs = s; bi = c; }
    }
}

__global__ void __launch_bounds__(256, 7) k_sel(const float* __restrict__ corners,
                                                const float* __restrict__ vp, int M,
                                                unsigned one) {
    __shared__ float ss[256];
    __shared__ int   si[256];
    __shared__ float sw[3];
    int r = blockIdx.x, tid = threadIdx.x;
    float bs = -3.4e38f; int bi = 0;
    const uint4* thv = reinterpret_cast<const uint4*>(g_bth);

    if (r < (int)RPRE) {
        /* precomputed rows: stream bits from DRAM, vectorized */
        const uint4* rowb = reinterpret_cast<const uint4*>(g_bits + (size_t)r * NC2);
        for (unsigned q = tid; q < NC2/4u; q += 256u) {
            uint4 v  = rowb[q];
            uint4 th = thv[q];
            int c = (int)(q * 4u);
            sel_try(v.x, th.x, c,   bs, bi);
            sel_try(v.y, th.y, c+1, bs, bi);
            sel_try(v.z, th.z, c+2, bs, bi);
            sel_try(v.w, th.w, c+3, bs, bi);
        }
    } else {
        /* inline threefry rows: 4 counters per iteration (ILP) */
        unsigned m13 = one << 13, m15 = one << 15;
        unsigned base = (unsigned)r * NC2;
        for (unsigned q = tid; q < NC2/4u; q += 256u) {
            unsigned j = base + q * 4u;
            unsigned o0, o1, o2, o3;
            tf_bits4(j, j+1u, j+2u, j+3u, o0, o1, o2, o3, one, m13, m15);
            uint4 th = thv[q];
            int c = (int)(q * 4u);
            sel_try(o0, th.x, c,   bs, bi);
            sel_try(o1, th.y, c+1, bs, bi);
            sel_try(o2, th.z, c+2, bs, bi);
            sel_try(o3, th.w, c+3, bs, bi);
        }
    }

    ss[tid] = bs; si[tid] = bi; __syncthreads();
    for (int o = 128; o > 0; o >>= 1) {
        if (tid < o) {
            float s2 = ss[tid+o]; int i2 = si[tid+o];
            if (s2 > ss[tid] || (s2 == ss[tid] && i2 < si[tid])) { ss[tid] = s2; si[tid] = i2; }
        }
        __syncthreads();
    }

    if (tid == 0) {
        int c  = si[0];
        int xi = c / GZ, zi = c - (c / GZ) * GZ;
        int yi = g_yidx[c];
        float wx = __fadd_rn(__fmul_rn((float)xi, RESF), corners[0]);
        float wy = __fadd_rn(__fmul_rn((float)yi, RESF), corners[1]);
        float wz = __fadd_rn(__fmul_rn((float)zi, RESF), corners[2]);
        g_world[3*r+0] = wx; g_world[3*r+1] = wy; g_world[3*r+2] = wz;
        sw[0] = wx; sw[1] = wy; sw[2] = wz;
        unsigned cell = ((unsigned)(xi*GY + yi))*GZ + (unsigned)zi;
        float4 gv = g_grid4[cell];
        float den = __fadd_rn(gv.x, 1e-7f);
        g_scout[3*r+0] = __fdiv_rn(gv.y, den);
        g_scout[3*r+1] = __fdiv_rn(gv.z, den);
        g_scout[3*r+2] = __fdiv_rn(gv.w, den);
    }
    __syncthreads();

    /* min distance to seed points for this row */
    float wx = sw[0], wy = sw[1], wz = sw[2];
    float mind = 3.4e38f;
    for (int m = tid; m < M; m += 256) {
        float dx = __fsub_rn(wx, vp[3*m]);
        float dy = __fsub_rn(wy, vp[3*m+1]);
        float dz = __fsub_rn(wz, vp[3*m+2]);
        float s  = __fadd_rn(__fadd_rn(__fmul_rn(dx,dx), __fmul_rn(dy,dy)), __fmul_rn(dz,dz));
        mind = fminf(mind, sqrtf(s));
    }
    ss[tid] = mind; __syncthreads();
    for (int o = 128; o > 0; o >>= 1) {
        if (tid < o) ss[tid] = fminf(ss[tid], ss[tid+o]);
        __syncthreads();
    }
    if (tid == 0) g_keep[r] = (ss[0] < 0.3f) ? 1 : 0;
}

/* ============ K6: parallel stable selection + output write ============ */
__global__ void __launch_bounds__(1024) k_finish(float* __restrict__ out) {
    __shared__ int sk[NROWS];
    int t = threadIdx.x;                       /* 1024 threads, one per row */
    int kp = g_keep[t];
    sk[t] = kp; __syncthreads();

    /* inclusive prefix sum of keep flags (Hillis-Steele) */
    for (int o = 1; o < NROWS; o <<= 1) {
        int val = sk[t];
        if (t >= o) val += sk[t - o];
        __syncthreads();
        sk[t] = val;
        __syncthreads();
    }
    int incl  = sk[t];
    int total = sk[NROWS - 1];

    /* output slot for this row under stable argsort(where(keep,0,1)) */
    int slot;
    if (total > 0) slot = kp ? (incl - 1) : (total + (t - incl));
    else           slot = t;                   /* keep.any()==False -> identity */

    if (slot < NPROP) {
        out[3*slot+0] = g_world[3*t+0];
        out[3*slot+1] = g_world[3*t+1];
        out[3*slot+2] = g_world[3*t+2];
        out[4*NPROP + 3*slot+0] = g_scout[3*t+0];
        out[4*NPROP + 3*slot+1] = g_scout[3*t+1];
        out[4*NPROP + 3*slot+2] = g_scout[3*t+2];
    }
    if (t < NPROP) out[3*NPROP + t] = 0.0f;    /* probs = zeros */
}

extern "C" void kernel_launch(void* const* d_in, const int* in_sizes, int n_in,
                              void* d_out, int out_size) {
    const float* pc      = (const float*)d_in[0];
    const float* xyz     = (const float*)d_in[1];
    const float* scale   = (const float*)d_in[2];
    const float* prob    = (const float*)d_in[3];
    const float* corners = (const float*)d_in[4];
    const float* vp      = (const float*)d_in[5];
    int N = in_sizes[0] / 3;
    int M = in_sizes[5] / 3;
    float* out = (float*)d_out;
    int vb = (N + 255) / 256;
    unsigned one = 1u;                          /* opaque to ptxas: pipe-balancing anchor */

    k_f1<<<PB1 + ZBLKS, 256>>>(one);
    k_f2<<<vb + PB2, 256>>>(pc, xyz, scale, prob, corners, N, vb, one);
    k_f3<<<CMBLKS + PB3, 256>>>(one);
    k_bth<<<CMBLKS, 256>>>();
    k_sel<<<NROWS, 256>>>(corners, vp, M, one);
    k_finish<<<1, 1024>>>(out);
}